// round 3
// baseline (speedup 1.0000x reference)
#include <cuda_runtime.h>
#include <math.h>

// ---------------- problem constants ----------------
constexpr int Bn    = 8;
constexpr int Cn    = 256;
constexpr int H_    = 256;
constexpr int W_    = 32;
constexpr int S_    = H_ * W_;      // 8192
constexpr int HEADS = 8;
constexpr int BHn   = Bn * HEADS;   // 64
constexpr int FFn   = 1024;
constexpr float EPSn = 1e-5f;

// ---------------- scratch (device globals; no runtime alloc) ----------------
__device__ float g_qkv [Bn * 768 * S_];   // 50,331,648
__device__ float g_bufa[Bn * Cn  * S_];   // attn branch image
__device__ float g_bufb[Bn * Cn  * S_];   // conv branch image
__device__ float g_bufc[Bn * Cn  * S_];   // attn-o / comb / ff2-raw
__device__ float g_ff1 [Bn * FFn * S_];   // 67,108,864
__device__ float g_ffdw[Bn * FFn * S_];
__device__ float g_cmean[Bn * S_];
__device__ float g_crstd[Bn * S_];
__device__ float g_rmean[Bn * FFn];
__device__ float g_rrstd[Bn * FFn];
__device__ float g_qprobe[BHn * 32];
__device__ float g_ksumH [BHn * 32 * 32];
__device__ float g_k2[BHn * 64 * 32];
__device__ float g_v2[BHn * 64 * 32];

// ---------------- channel layernorm stats (over C for each (b,s)) ----------------
__global__ void cln_stats_kernel(const float* __restrict__ x,
                                 float* __restrict__ mean, float* __restrict__ rstd) {
    int b = blockIdx.x / (S_ / 256);
    int s = (blockIdx.x % (S_ / 256)) * 256 + threadIdx.x;
    const float* p = x + (size_t)b * Cn * S_ + s;
    float sum = 0.f, sq = 0.f;
#pragma unroll 4
    for (int c = 0; c < Cn; ++c) {
        float v = p[(size_t)c * S_];
        sum += v; sq += v * v;
    }
    float m = sum * (1.f / Cn);
    float var = sq * (1.f / Cn) - m * m;
    mean[b * S_ + s] = m;
    rstd[b * S_ + s] = rsqrtf(var + EPSn);
}

// ---------------- generic fp32 GEMM: Out[b,n,s] = act(sum_k W[n,k]*A[b,k,s]) ----------------
// MODE 0: plain A0;  MODE 1: channel-LN transform of A0 on load;  MODE 2: concat(A0,A1) on k
template<int MODE, bool RES>
__global__ __launch_bounds__(256) void gemm_kernel(
    const float* __restrict__ A0, const float* __restrict__ A1,
    const float* __restrict__ Wt, const float* __restrict__ bias,
    const float* __restrict__ resid,
    const float* __restrict__ cmean, const float* __restrict__ crstd,
    const float* __restrict__ gamma, const float* __restrict__ beta,
    float* __restrict__ Out, int K, int N)
{
    __shared__ float Ws[16 * 132];
    __shared__ float As[16 * 132];
    const int b  = blockIdx.z;
    const int s0 = blockIdx.x * 128;
    const int n0 = blockIdx.y * 128;
    const int t  = threadIdx.x;
    const int tx = t & 15, ty = t >> 4;

    float acc[8][8];
#pragma unroll
    for (int i = 0; i < 8; ++i)
#pragma unroll
        for (int j = 0; j < 8; ++j) acc[i][j] = 0.f;

    const int wkq = (t & 3) * 4;
    const int wn  = t >> 2;
    const int asl = (t & 31) * 4;
    const int akl = t >> 5;

    for (int k0 = 0; k0 < K; k0 += 16) {
#pragma unroll
        for (int pass = 0; pass < 2; ++pass) {
            int n = wn + pass * 64;
            float4 w4 = *reinterpret_cast<const float4*>(Wt + (size_t)(n0 + n) * K + k0 + wkq);
            Ws[(wkq + 0) * 132 + n] = w4.x;
            Ws[(wkq + 1) * 132 + n] = w4.y;
            Ws[(wkq + 2) * 132 + n] = w4.z;
            Ws[(wkq + 3) * 132 + n] = w4.w;
        }
#pragma unroll
        for (int pass = 0; pass < 2; ++pass) {
            int k  = akl + pass * 8;
            int kg = k0 + k;
            float4 a4;
            if (MODE == 2) {
                const float* src = (kg < 256)
                    ? (A0 + ((size_t)b * 256 + kg) * S_)
                    : (A1 + ((size_t)b * 256 + (kg - 256)) * S_);
                a4 = *reinterpret_cast<const float4*>(src + s0 + asl);
            } else {
                a4 = *reinterpret_cast<const float4*>(A0 + ((size_t)b * K + kg) * S_ + s0 + asl);
            }
            if (MODE == 1) {
                float4 m4 = *reinterpret_cast<const float4*>(cmean + (size_t)b * S_ + s0 + asl);
                float4 r4 = *reinterpret_cast<const float4*>(crstd + (size_t)b * S_ + s0 + asl);
                float g = gamma[kg], be = beta[kg];
                a4.x = (a4.x - m4.x) * r4.x * g + be;
                a4.y = (a4.y - m4.y) * r4.y * g + be;
                a4.z = (a4.z - m4.z) * r4.z * g + be;
                a4.w = (a4.w - m4.w) * r4.w * g + be;
            }
            *reinterpret_cast<float4*>(As + k * 132 + asl) = a4;
        }
        __syncthreads();
#pragma unroll
        for (int kk = 0; kk < 16; ++kk) {
            float4 w0 = *reinterpret_cast<const float4*>(Ws + kk * 132 + ty * 4);
            float4 w1 = *reinterpret_cast<const float4*>(Ws + kk * 132 + 64 + ty * 4);
            float4 x0 = *reinterpret_cast<const float4*>(As + kk * 132 + tx * 4);
            float4 x1 = *reinterpret_cast<const float4*>(As + kk * 132 + 64 + tx * 4);
            float wv[8] = {w0.x, w0.y, w0.z, w0.w, w1.x, w1.y, w1.z, w1.w};
            float xv[8] = {x0.x, x0.y, x0.z, x0.w, x1.x, x1.y, x1.z, x1.w};
#pragma unroll
            for (int i = 0; i < 8; ++i)
#pragma unroll
                for (int j = 0; j < 8; ++j)
                    acc[i][j] = fmaf(wv[i], xv[j], acc[i][j]);
        }
        __syncthreads();
    }

#pragma unroll
    for (int i = 0; i < 8; ++i) {
        int n = n0 + ((i < 4) ? (ty * 4 + i) : (64 + ty * 4 + i - 4));
        float bv = (bias != nullptr) ? bias[n] : 0.f;
#pragma unroll
        for (int jh = 0; jh < 2; ++jh) {
            int s = s0 + jh * 64 + tx * 4;
            float4 o;
            o.x = acc[i][jh * 4 + 0] + bv;
            o.y = acc[i][jh * 4 + 1] + bv;
            o.z = acc[i][jh * 4 + 2] + bv;
            o.w = acc[i][jh * 4 + 3] + bv;
            if (RES) {
                float4 r = *reinterpret_cast<const float4*>(resid + ((size_t)b * N + n) * S_ + s);
                o.x += r.x; o.y += r.y; o.z += r.z; o.w += r.w;
            }
            *reinterpret_cast<float4*>(Out + ((size_t)b * N + n) * S_ + s) = o;
        }
    }
}

// ---------------- L2 normalize q and k rows over W (32 contiguous) ----------------
__global__ void l2norm_kernel(float* __restrict__ qkv) {
    int gw   = (blockIdx.x * blockDim.x + threadIdx.x) >> 5; // row id
    int lane = threadIdx.x & 31;
    int x  = gw % H_;
    int ch = (gw / H_) % 512;            // q: 0..255, k: 256..511
    int b  = gw / (H_ * 512);
    float* p = qkv + ((size_t)b * 768 + ch) * S_ + x * W_ + lane;
    float v = *p;
    float sq = v * v;
#pragma unroll
    for (int o = 16; o > 0; o >>= 1) sq += __shfl_xor_sync(0xffffffffu, sq, o);
    float nrm = fmaxf(sqrtf(sq), 1e-12f);
    *p = v / nrm;
}

// ---------------- q_probe[bh,y] = sum_{dh,x} qn ----------------
__global__ void qprobe_kernel(const float* __restrict__ qkv, float* __restrict__ qprobe) {
    int bh = blockIdx.x; int b = bh >> 3, head = bh & 7;
    int t = threadIdx.x, y = t & 31, part = t >> 5;
    const float* base = qkv + ((size_t)b * 768 + head * 32) * S_;
    float acc = 0.f;
    for (int r = part * 1024; r < part * 1024 + 1024; ++r) {
        int dh = r >> 8, x = r & 255;
        acc += base[(size_t)dh * S_ + x * 32 + y];
    }
    __shared__ float sh[256];
    sh[t] = acc;
    __syncthreads();
    if (t < 32) {
        float s = 0.f;
#pragma unroll
        for (int p = 0; p < 8; ++p) s += sh[p * 32 + t];
        qprobe[bh * 32 + t] = s;
    }
}

// ---------------- ksumH[bh,dh,y] = sum_x kn ----------------
__global__ void ksumh_kernel(const float* __restrict__ qkv, float* __restrict__ ksumH) {
    int idx = blockIdx.x * blockDim.x + threadIdx.x;  // BHn*32*32
    int y = idx & 31, dh = (idx >> 5) & 31, bh = idx >> 10;
    int b = bh >> 3, head = bh & 7;
    const float* p = qkv + ((size_t)b * 768 + 256 + head * 32 + dh) * S_ + y;
    float s = 0.f;
    for (int x = 0; x < H_; ++x) s += p[x * 32];
    ksumH[idx] = s;
}

// ---------------- top-k selection + gather of k2/v2 (one block per bh) ----------------
__global__ void select_kernel(const float* __restrict__ qkv,
                              const float* __restrict__ qprobe,
                              const float* __restrict__ ksumH,
                              float* __restrict__ k2, float* __restrict__ v2) {
    int bh = blockIdx.x; int b = bh >> 3, head = bh & 7;
    int t = threadIdx.x;
    __shared__ float qp[32];
    __shared__ float shs[32];
    __shared__ int   ih[8];
    __shared__ float sws[256];
    __shared__ int   iw[8];

    if (t < 32) qp[t] = qprobe[bh * 32 + t];
    __syncthreads();
    if (t < 32) {
        float s = 0.f;
        const float* kr = ksumH + (bh * 32 + t) * 32;
#pragma unroll
        for (int y = 0; y < 32; ++y) s += qp[y] * kr[y];
        shs[t] = s;
    }
    __syncthreads();
    if (t == 0) {
        for (int j = 0; j < 8; ++j) {
            float best = -INFINITY; int bi = 0;
            for (int i = 0; i < 32; ++i)
                if (shs[i] > best) { best = shs[i]; bi = i; }
            ih[j] = bi; shs[bi] = -INFINITY;
        }
    }
    __syncthreads();
    {   // sw[x] over spatial-H, summed over selected dh
        int x = t;
        float s = 0.f;
        const float* kbase = qkv + ((size_t)b * 768 + 256 + head * 32) * S_ + x * 32;
        for (int j = 0; j < 8; ++j) {
            const float* kp = kbase + (size_t)ih[j] * S_;
#pragma unroll
            for (int y = 0; y < 32; ++y) s += kp[y] * qp[y];
        }
        sws[x] = s;
    }
    __syncthreads();
    if (t == 0) {
        for (int j = 0; j < 8; ++j) {
            float best = -INFINITY; int bi = 0;
            for (int i = 0; i < 256; ++i)
                if (sws[i] > best) { best = sws[i]; bi = i; }
            iw[j] = bi; sws[bi] = -INFINITY;
        }
    }
    __syncthreads();
    for (int e = t; e < 64 * 32; e += 256) {
        int j = e >> 5, y = e & 31;
        int dh = ih[j >> 3], x = iw[j & 7];
        size_t koff = ((size_t)b * 768 + 256 + head * 32 + dh) * S_ + x * 32 + y;
        k2[(bh * 64 + j) * 32 + y] = qkv[koff];
        v2[(bh * 64 + j) * 32 + y] = qkv[koff + (size_t)256 * S_];
    }
}

// ---------------- attention: 8192 rows x 64 keys per bh ----------------
__global__ __launch_bounds__(256) void attn_kernel(const float* __restrict__ qkv,
                                                   const float* __restrict__ k2g,
                                                   const float* __restrict__ v2g,
                                                   float* __restrict__ outimg) {
    int bh = blockIdx.y; int b = bh >> 3, head = bh & 7;
    int i0 = blockIdx.x * 32;
    int t = threadIdx.x, w = t >> 5, lane = t & 31;
    __shared__ float k2s[64 * 33];
    __shared__ float v2s[64 * 33];
    __shared__ float tile[32 * 33];
    for (int e = t; e < 64 * 32; e += 256) {
        int j = e >> 5, y = e & 31;
        k2s[j * 33 + y] = k2g[(bh * 64 + j) * 32 + y];
        v2s[j * 33 + y] = v2g[(bh * 64 + j) * 32 + y];
    }
    __syncthreads();
    const float* qbase = qkv + ((size_t)b * 768 + head * 32) * S_;
    for (int r = w; r < 32; r += 8) {
        int i  = i0 + r;
        int dh = i >> 8, x = i & 255;
        float qv = qbase[(size_t)dh * S_ + x * 32 + lane];
        float s0 = 0.f, s1 = 0.f;
#pragma unroll
        for (int y = 0; y < 32; ++y) {
            float qy = __shfl_sync(0xffffffffu, qv, y);
            s0 = fmaf(qy, k2s[lane * 33 + y], s0);
            s1 = fmaf(qy, k2s[(lane + 32) * 33 + y], s1);
        }
        float m = fmaxf(s0, s1);
#pragma unroll
        for (int o = 16; o > 0; o >>= 1) m = fmaxf(m, __shfl_xor_sync(0xffffffffu, m, o));
        float p0 = expf(s0 - m), p1 = expf(s1 - m);
        float sum = p0 + p1;
#pragma unroll
        for (int o = 16; o > 0; o >>= 1) sum += __shfl_xor_sync(0xffffffffu, sum, o);
        float inv = 1.f / sum;
        p0 *= inv; p1 *= inv;
        float o = 0.f;
#pragma unroll
        for (int j = 0; j < 32; ++j) {
            float pj = __shfl_sync(0xffffffffu, p0, j);
            o = fmaf(pj, v2s[j * 33 + lane], o);
        }
#pragma unroll
        for (int j = 0; j < 32; ++j) {
            float pj = __shfl_sync(0xffffffffu, p1, j);
            o = fmaf(pj, v2s[(j + 32) * 33 + lane], o);
        }
        tile[r * 33 + lane] = o;
    }
    __syncthreads();
    // out channel = head*32 + d, spatial index = i
    for (int e = t; e < 1024; e += 256) {
        int d = e >> 5, rr = e & 31;
        outimg[((size_t)b * 256 + head * 32 + d) * S_ + i0 + rr] = tile[rr * 33 + d];
    }
}

// ---------------- depthwise 3x3, SAME, per-channel ----------------
__global__ void dwconv_kernel(const float* __restrict__ in, const float* __restrict__ wgt,
                              const float* __restrict__ bias, float* __restrict__ out, int Cch) {
    int idx = blockIdx.x * blockDim.x + threadIdx.x;
    int s = idx & (S_ - 1);
    int c = (idx >> 13) % Cch;
    int b = idx / (Cch * S_);
    int h = s >> 5, wv = s & 31;
    const float* p  = in + ((size_t)b * Cch + c) * S_;
    const float* wp = wgt + c * 9;
    float acc = bias[c];
#pragma unroll
    for (int dy = -1; dy <= 1; ++dy) {
        int h2 = h + dy;
        if (h2 < 0 || h2 >= H_) continue;
#pragma unroll
        for (int dx = -1; dx <= 1; ++dx) {
            int w2 = wv + dx;
            if (w2 < 0 || w2 >= W_) continue;
            acc = fmaf(wp[(dy + 1) * 3 + (dx + 1)], p[h2 * 32 + w2], acc);
        }
    }
    out[idx] = acc;
}

// ---------------- instance-norm row stats (per (b,c) over S) ----------------
__global__ void rowstats_kernel(const float* __restrict__ v,
                                float* __restrict__ mean, float* __restrict__ rstd) {
    int row = blockIdx.x;
    const float* p = v + (size_t)row * S_;
    int t = threadIdx.x;
    float sum = 0.f, sq = 0.f;
    for (int i = t; i < S_; i += 256) { float x = p[i]; sum += x; sq += x * x; }
    __shared__ float s1[256], s2[256];
    s1[t] = sum; s2[t] = sq; __syncthreads();
    for (int o = 128; o > 0; o >>= 1) {
        if (t < o) { s1[t] += s1[t + o]; s2[t] += s2[t + o]; }
        __syncthreads();
    }
    if (t == 0) {
        float m = s1[0] * (1.f / S_);
        float var = s2[0] * (1.f / S_) - m * m;
        mean[row] = m; rstd[row] = rsqrtf(var + EPSn);
    }
}

// MODE 0: gelu(norm);  MODE 1: addsrc + gelu(norm);  MODE 2: norm only
template<int MODE>
__global__ void inorm_apply_kernel(const float* __restrict__ src, const float* __restrict__ addsrc,
                                   const float* __restrict__ mean, const float* __restrict__ rstd,
                                   float* __restrict__ dst) {
    int idx = blockIdx.x * blockDim.x + threadIdx.x;
    int row = idx >> 13;
    float x = (src[idx] - mean[row]) * rstd[row];
    if (MODE <= 1) x = 0.5f * x * (1.f + erff(x * 0.7071067811865475f));
    if (MODE == 1) x += addsrc[idx];
    dst[idx] = x;
}

// ---------------- host orchestration ----------------
extern "C" void kernel_launch(void* const* d_in, const int* in_sizes, int n_in,
                              void* d_out, int out_size) {
    const float* x      = (const float*)d_in[0];
    const float* cg     = (const float*)d_in[1];
    const float* cb     = (const float*)d_in[2];
    const float* w_qkv  = (const float*)d_in[3];
    const float* w_out  = (const float*)d_in[4];
    const float* b_out  = (const float*)d_in[5];
    const float* w_dw   = (const float*)d_in[6];
    const float* b_dw   = (const float*)d_in[7];
    const float* w_comb = (const float*)d_in[8];
    const float* b_comb = (const float*)d_in[9];
    const float* w_ff1  = (const float*)d_in[10];
    const float* b_ff1  = (const float*)d_in[11];
    const float* w_ffdw = (const float*)d_in[12];
    const float* b_ffdw = (const float*)d_in[13];
    const float* w_ff2  = (const float*)d_in[14];
    const float* b_ff2  = (const float*)d_in[15];
    float* out = (float*)d_out;

    float *qkv, *bufa, *bufb, *bufc, *ff1, *ffdw;
    float *cmean, *crstd, *rmean, *rrstd, *qprobe, *ksumH, *k2, *v2;
    void* p;
    cudaGetSymbolAddress(&p, g_qkv);    qkv    = (float*)p;
    cudaGetSymbolAddress(&p, g_bufa);   bufa   = (float*)p;
    cudaGetSymbolAddress(&p, g_bufb);   bufb   = (float*)p;
    cudaGetSymbolAddress(&p, g_bufc);   bufc   = (float*)p;
    cudaGetSymbolAddress(&p, g_ff1);    ff1    = (float*)p;
    cudaGetSymbolAddress(&p, g_ffdw);   ffdw   = (float*)p;
    cudaGetSymbolAddress(&p, g_cmean);  cmean  = (float*)p;
    cudaGetSymbolAddress(&p, g_crstd);  crstd  = (float*)p;
    cudaGetSymbolAddress(&p, g_rmean);  rmean  = (float*)p;
    cudaGetSymbolAddress(&p, g_rrstd);  rrstd  = (float*)p;
    cudaGetSymbolAddress(&p, g_qprobe); qprobe = (float*)p;
    cudaGetSymbolAddress(&p, g_ksumH);  ksumH  = (float*)p;
    cudaGetSymbolAddress(&p, g_k2);     k2     = (float*)p;
    cudaGetSymbolAddress(&p, g_v2);     v2     = (float*)p;

    // 1) channel layernorm stats
    cln_stats_kernel<<<Bn * S_ / 256, 256>>>(x, cmean, crstd);

    // 2) qkv = conv1x1(CLN(x), w_qkv)   (no bias)
    gemm_kernel<1, false><<<dim3(S_ / 128, 768 / 128, Bn), 256>>>(
        x, nullptr, w_qkv, nullptr, nullptr, cmean, crstd, cg, cb, qkv, 256, 768);

    // 3) L2-normalize q and k rows (over W)
    l2norm_kernel<<<(Bn * 512 * H_) / 8, 256>>>(qkv);

    // 4) probe sums + key reductions
    qprobe_kernel<<<BHn, 256>>>(qkv, qprobe);
    ksumh_kernel<<<(BHn * 32 * 32) / 256, 256>>>(qkv, ksumH);

    // 5) top-k selection + gather of 64 key/value vectors per bh
    select_kernel<<<BHn, 256>>>(qkv, qprobe, ksumH, k2, v2);

    // 6) attention -> o image (bufc)
    attn_kernel<<<dim3(S_ / 32, BHn), 256>>>(qkv, k2, v2, bufc);

    // 7) attn branch: conv1x1(o, w_out) + b_out -> bufa
    gemm_kernel<0, false><<<dim3(S_ / 128, 256 / 128, Bn), 256>>>(
        bufc, nullptr, w_out, b_out, nullptr, nullptr, nullptr, nullptr, nullptr, bufa, 256, 256);

    // 8) conv branch: depthwise 3x3 on x -> bufb
    dwconv_kernel<<<(Bn * Cn * S_) / 256, 256>>>(x, w_dw, b_dw, bufb, Cn);

    // 9) combine: conv1x1(concat(bufa,bufb), w_comb) + b_comb + x -> bufc
    gemm_kernel<2, true><<<dim3(S_ / 128, 256 / 128, Bn), 256>>>(
        bufa, bufb, w_comb, b_comb, x, nullptr, nullptr, nullptr, nullptr, bufc, 512, 256);

    // 10) ff1: conv1x1 -> instance norm -> gelu  (in-place on ff1)
    gemm_kernel<0, false><<<dim3(S_ / 128, FFn / 128, Bn), 256>>>(
        bufc, nullptr, w_ff1, b_ff1, nullptr, nullptr, nullptr, nullptr, nullptr, ff1, 256, FFn);
    rowstats_kernel<<<Bn * FFn, 256>>>(ff1, rmean, rrstd);
    inorm_apply_kernel<0><<<(Bn * FFn * S_) / 256, 256>>>(ff1, nullptr, rmean, rrstd, ff1);

    // 11) ff depthwise: h2 = h1 + gelu(inorm(dw3x3(h1)))  -> ffdw
    dwconv_kernel<<<(Bn * FFn * S_) / 256, 256>>>(ff1, w_ffdw, b_ffdw, ffdw, FFn);
    rowstats_kernel<<<Bn * FFn, 256>>>(ffdw, rmean, rrstd);
    inorm_apply_kernel<1><<<(Bn * FFn * S_) / 256, 256>>>(ffdw, ff1, rmean, rrstd, ffdw);

    // 12) ff2: conv1x1 -> instance norm -> d_out
    gemm_kernel<0, false><<<dim3(S_ / 128, 256 / 128, Bn), 256>>>(
        ffdw, nullptr, w_ff2, b_ff2, nullptr, nullptr, nullptr, nullptr, nullptr, bufc, FFn, 256);
    rowstats_kernel<<<Bn * Cn, 256>>>(bufc, rmean, rrstd);
    inorm_apply_kernel<2><<<(Bn * Cn * S_) / 256, 256>>>(bufc, nullptr, rmean, rrstd, out);
}

// round 4
// speedup vs baseline: 1.3597x; 1.3597x over previous
#include <cuda_runtime.h>
#include <math.h>
#include <stdint.h>

// ---------------- problem constants ----------------
constexpr int Bn    = 8;
constexpr int Cn    = 256;
constexpr int H_    = 256;
constexpr int W_    = 32;
constexpr int S_    = H_ * W_;      // 8192
constexpr int HEADS = 8;
constexpr int BHn   = Bn * HEADS;   // 64
constexpr int FFn   = 1024;
constexpr float EPSn = 1e-5f;

// ---------------- scratch (device globals; no runtime alloc) ----------------
__device__ float g_qkv [Bn * 768 * S_];
__device__ float g_bufa[Bn * Cn  * S_];
__device__ float g_bufb[Bn * Cn  * S_];
__device__ float g_bufc[Bn * Cn  * S_];
__device__ float g_ff1 [Bn * FFn * S_];
__device__ float g_ffdw[Bn * FFn * S_];
__device__ float g_cmean[Bn * S_];
__device__ float g_crstd[Bn * S_];
__device__ float g_rmean[Bn * FFn];
__device__ float g_rrstd[Bn * FFn];
__device__ float g_qpart[BHn * 8 * 32];
__device__ float g_ksumH [BHn * 32 * 32];
__device__ float g_k2[BHn * 64 * 32];
__device__ float g_v2[BHn * 64 * 32];

// ---------------- helpers ----------------
__device__ __forceinline__ float to_tf32(float x) {
    uint32_t u;
    asm("cvt.rna.tf32.f32 %0, %1;" : "=r"(u) : "f"(x));
    return __uint_as_float(u);
}

__device__ __forceinline__ void mma_tf32(float* d, const uint32_t* a, const uint32_t* bm) {
    asm volatile(
        "mma.sync.aligned.m16n8k8.row.col.f32.tf32.tf32.f32 "
        "{%0,%1,%2,%3}, {%4,%5,%6,%7}, {%8,%9}, {%0,%1,%2,%3};"
        : "+f"(d[0]), "+f"(d[1]), "+f"(d[2]), "+f"(d[3])
        : "r"(a[0]), "r"(a[1]), "r"(a[2]), "r"(a[3]), "r"(bm[0]), "r"(bm[1]));
}

// ---------------- channel layernorm stats (over C for each (b,s)) ----------------
__global__ void cln_stats_kernel(const float* __restrict__ x,
                                 float* __restrict__ mean, float* __restrict__ rstd) {
    int b = blockIdx.x / (S_ / 256);
    int s = (blockIdx.x % (S_ / 256)) * 256 + threadIdx.x;
    const float* p = x + (size_t)b * Cn * S_ + s;
    float sum = 0.f, sq = 0.f;
#pragma unroll 4
    for (int c = 0; c < Cn; ++c) {
        float v = p[(size_t)c * S_];
        sum += v; sq += v * v;
    }
    float m = sum * (1.f / Cn);
    float var = sq * (1.f / Cn) - m * m;
    mean[b * S_ + s] = m;
    rstd[b * S_ + s] = rsqrtf(var + EPSn);
}

// ---------------- tf32 tensor-core GEMM: Out[b,n,s] = sum_k W[n,k]*A[b,k,s] ----------------
// MODE 0: plain A0;  MODE 1: channel-LN transform of A0 on load;  MODE 2: concat(A0,A1) on k
template<int MODE, bool RES>
__global__ __launch_bounds__(256) void gemm_tf32_kernel(
    const float* __restrict__ A0, const float* __restrict__ A1,
    const float* __restrict__ Wt, const float* __restrict__ bias,
    const float* __restrict__ resid,
    const float* __restrict__ cmean, const float* __restrict__ crstd,
    const float* __restrict__ gamma, const float* __restrict__ beta,
    float* __restrict__ Out, int K, int N)
{
    __shared__ float Ws[16 * 132];   // [k][n]
    __shared__ float As[16 * 132];   // [k][s]
    const int b  = blockIdx.z;
    const int s0 = blockIdx.x * 128;
    const int n0 = blockIdx.y * 128;
    const int t  = threadIdx.x;
    const int lane = t & 31, warp = t >> 5;
    const int wn = warp & 3, ws = warp >> 2;
    const int n0w = wn * 32, s0w = ws * 64;
    const int r = lane >> 2, c = lane & 3;

    float acc[2][8][4];
#pragma unroll
    for (int mt = 0; mt < 2; ++mt)
#pragma unroll
        for (int nt = 0; nt < 8; ++nt)
#pragma unroll
            for (int q = 0; q < 4; ++q) acc[mt][nt][q] = 0.f;

    const int wkq = (t & 3) * 4;
    const int wnl = t >> 2;
    const int asl = (t & 31) * 4;
    const int akl = t >> 5;

    for (int k0 = 0; k0 < K; k0 += 16) {
#pragma unroll
        for (int pass = 0; pass < 2; ++pass) {
            int n = wnl + pass * 64;
            float4 w4 = *reinterpret_cast<const float4*>(Wt + (size_t)(n0 + n) * K + k0 + wkq);
            Ws[(wkq + 0) * 132 + n] = to_tf32(w4.x);
            Ws[(wkq + 1) * 132 + n] = to_tf32(w4.y);
            Ws[(wkq + 2) * 132 + n] = to_tf32(w4.z);
            Ws[(wkq + 3) * 132 + n] = to_tf32(w4.w);
        }
#pragma unroll
        for (int pass = 0; pass < 2; ++pass) {
            int k  = akl + pass * 8;
            int kg = k0 + k;
            float4 a4;
            if (MODE == 2) {
                const float* src = (kg < 256)
                    ? (A0 + ((size_t)b * 256 + kg) * S_)
                    : (A1 + ((size_t)b * 256 + (kg - 256)) * S_);
                a4 = *reinterpret_cast<const float4*>(src + s0 + asl);
            } else {
                a4 = *reinterpret_cast<const float4*>(A0 + ((size_t)b * K + kg) * S_ + s0 + asl);
            }
            if (MODE == 1) {
                float4 m4 = *reinterpret_cast<const float4*>(cmean + (size_t)b * S_ + s0 + asl);
                float4 r4 = *reinterpret_cast<const float4*>(crstd + (size_t)b * S_ + s0 + asl);
                float g = gamma[kg], be = beta[kg];
                a4.x = (a4.x - m4.x) * r4.x * g + be;
                a4.y = (a4.y - m4.y) * r4.y * g + be;
                a4.z = (a4.z - m4.z) * r4.z * g + be;
                a4.w = (a4.w - m4.w) * r4.w * g + be;
            }
            As[k * 132 + asl + 0] = to_tf32(a4.x);
            As[k * 132 + asl + 1] = to_tf32(a4.y);
            As[k * 132 + asl + 2] = to_tf32(a4.z);
            As[k * 132 + asl + 3] = to_tf32(a4.w);
        }
        __syncthreads();
#pragma unroll
        for (int kk = 0; kk < 16; kk += 8) {
            uint32_t af[2][4];
#pragma unroll
            for (int mt = 0; mt < 2; ++mt) {
                int row = n0w + mt * 16 + r;
                af[mt][0] = __float_as_uint(Ws[(kk + c) * 132 + row]);
                af[mt][1] = __float_as_uint(Ws[(kk + c) * 132 + row + 8]);
                af[mt][2] = __float_as_uint(Ws[(kk + c + 4) * 132 + row]);
                af[mt][3] = __float_as_uint(Ws[(kk + c + 4) * 132 + row + 8]);
            }
            uint32_t bf[8][2];
#pragma unroll
            for (int nt = 0; nt < 8; ++nt) {
                int col = s0w + nt * 8 + r;
                bf[nt][0] = __float_as_uint(As[(kk + c) * 132 + col]);
                bf[nt][1] = __float_as_uint(As[(kk + c + 4) * 132 + col]);
            }
#pragma unroll
            for (int mt = 0; mt < 2; ++mt)
#pragma unroll
                for (int nt = 0; nt < 8; ++nt)
                    mma_tf32(acc[mt][nt], af[mt], bf[nt]);
        }
        __syncthreads();
    }

    // epilogue: c0=(r,2c) c1=(r,2c+1) c2=(r+8,2c) c3=(r+8,2c+1)
#pragma unroll
    for (int mt = 0; mt < 2; ++mt) {
#pragma unroll
        for (int half = 0; half < 2; ++half) {
            int n = n0 + n0w + mt * 16 + r + half * 8;
            float bv = (bias != nullptr) ? bias[n] : 0.f;
            float* orow = Out + ((size_t)b * N + n) * S_;
            const float* rrow = RES ? (resid + ((size_t)b * N + n) * S_) : nullptr;
#pragma unroll
            for (int nt = 0; nt < 8; ++nt) {
                int s = s0 + s0w + nt * 8 + 2 * c;
                float2 o;
                o.x = acc[mt][nt][half * 2 + 0] + bv;
                o.y = acc[mt][nt][half * 2 + 1] + bv;
                if (RES) {
                    float2 rv = *reinterpret_cast<const float2*>(rrow + s);
                    o.x += rv.x; o.y += rv.y;
                }
                *reinterpret_cast<float2*>(orow + s) = o;
            }
        }
    }
}

// ---------------- L2 normalize q and k rows over W (32 contiguous) ----------------
__global__ void l2norm_kernel(float* __restrict__ qkv) {
    int gw   = (blockIdx.x * blockDim.x + threadIdx.x) >> 5;
    int lane = threadIdx.x & 31;
    int x  = gw % H_;
    int ch = (gw / H_) % 512;
    int b  = gw / (H_ * 512);
    float* p = qkv + ((size_t)b * 768 + ch) * S_ + x * W_ + lane;
    float v = *p;
    float sq = v * v;
#pragma unroll
    for (int o = 16; o > 0; o >>= 1) sq += __shfl_xor_sync(0xffffffffu, sq, o);
    float nrm = fmaxf(sqrtf(sq), 1e-12f);
    *p = v / nrm;
}

// ---------------- q_probe partials: qpart[bh,part,y] over x-chunk, all dh ----------------
__global__ void qprobe_kernel(const float* __restrict__ qkv, float* __restrict__ qpart) {
    int bp = blockIdx.x;
    int bh = bp >> 3, part = bp & 7;
    int b = bh >> 3, head = bh & 7;
    int t = threadIdx.x, y = t & 31, sub = t >> 5;
    const float* base = qkv + ((size_t)b * 768 + head * 32) * S_;
    float acc = 0.f;
    // rows: 32 dh x 32 x-positions (x in [part*32, part*32+32)); 8 subs x 128 rows
    for (int rr = sub * 128; rr < sub * 128 + 128; ++rr) {
        int dh = rr >> 5;
        int x  = part * 32 + (rr & 31);
        acc += base[(size_t)dh * S_ + x * 32 + y];
    }
    __shared__ float sh[256];
    sh[t] = acc;
    __syncthreads();
    if (t < 32) {
        float s = 0.f;
#pragma unroll
        for (int p = 0; p < 8; ++p) s += sh[p * 32 + t];
        qpart[bp * 32 + t] = s;
    }
}

// ---------------- ksumH[bh,dh,y] = sum_x kn ----------------
__global__ void ksumh_kernel(const float* __restrict__ qkv, float* __restrict__ ksumH) {
    int idx = blockIdx.x * blockDim.x + threadIdx.x;
    int y = idx & 31, dh = (idx >> 5) & 31, bh = idx >> 10;
    int b = bh >> 3, head = bh & 7;
    const float* p = qkv + ((size_t)b * 768 + 256 + head * 32 + dh) * S_ + y;
    float s = 0.f;
    for (int x = 0; x < H_; ++x) s += p[x * 32];
    ksumH[idx] = s;
}

// ---------------- top-k selection + gather of k2/v2 (one block per bh) ----------------
__global__ void select_kernel(const float* __restrict__ qkv,
                              const float* __restrict__ qpart,
                              const float* __restrict__ ksumH,
                              float* __restrict__ k2, float* __restrict__ v2) {
    int bh = blockIdx.x; int b = bh >> 3, head = bh & 7;
    int t = threadIdx.x;
    __shared__ float qp[32];
    __shared__ float shs[32];
    __shared__ int   ih[8];
    __shared__ float sws[256];
    __shared__ int   iw[8];

    if (t < 32) {
        float s = 0.f;
#pragma unroll
        for (int p = 0; p < 8; ++p) s += qpart[(bh * 8 + p) * 32 + t];
        qp[t] = s;
    }
    __syncthreads();
    if (t < 32) {
        float s = 0.f;
        const float* kr = ksumH + (bh * 32 + t) * 32;
#pragma unroll
        for (int y = 0; y < 32; ++y) s += qp[y] * kr[y];
        shs[t] = s;
    }
    __syncthreads();
    if (t == 0) {
        for (int j = 0; j < 8; ++j) {
            float best = -INFINITY; int bi = 0;
            for (int i = 0; i < 32; ++i)
                if (shs[i] > best) { best = shs[i]; bi = i; }
            ih[j] = bi; shs[bi] = -INFINITY;
        }
    }
    __syncthreads();
    {
        int x = t;
        float s = 0.f;
        const float* kbase = qkv + ((size_t)b * 768 + 256 + head * 32) * S_ + x * 32;
        for (int j = 0; j < 8; ++j) {
            const float* kp = kbase + (size_t)ih[j] * S_;
#pragma unroll
            for (int y = 0; y < 32; ++y) s += kp[y] * qp[y];
        }
        sws[x] = s;
    }
    __syncthreads();
    if (t == 0) {
        for (int j = 0; j < 8; ++j) {
            float best = -INFINITY; int bi = 0;
            for (int i = 0; i < 256; ++i)
                if (sws[i] > best) { best = sws[i]; bi = i; }
            iw[j] = bi; sws[bi] = -INFINITY;
        }
    }
    __syncthreads();
    for (int e = t; e < 64 * 32; e += 256) {
        int j = e >> 5, y = e & 31;
        int dh = ih[j >> 3], x = iw[j & 7];
        size_t koff = ((size_t)b * 768 + 256 + head * 32 + dh) * S_ + x * 32 + y;
        k2[(bh * 64 + j) * 32 + y] = qkv[koff];
        v2[(bh * 64 + j) * 32 + y] = qkv[koff + (size_t)256 * S_];
    }
}

// ---------------- attention: 8192 rows x 64 keys per bh ----------------
__global__ __launch_bounds__(256) void attn_kernel(const float* __restrict__ qkv,
                                                   const float* __restrict__ k2g,
                                                   const float* __restrict__ v2g,
                                                   float* __restrict__ outimg) {
    int bh = blockIdx.y; int b = bh >> 3, head = bh & 7;
    int i0 = blockIdx.x * 32;
    int t = threadIdx.x, w = t >> 5, lane = t & 31;
    __shared__ float k2s[64 * 33];
    __shared__ float v2s[64 * 33];
    __shared__ float tile[32 * 33];
    for (int e = t; e < 64 * 32; e += 256) {
        int j = e >> 5, y = e & 31;
        k2s[j * 33 + y] = k2g[(bh * 64 + j) * 32 + y];
        v2s[j * 33 + y] = v2g[(bh * 64 + j) * 32 + y];
    }
    __syncthreads();
    const float* qbase = qkv + ((size_t)b * 768 + head * 32) * S_;
    for (int r = w; r < 32; r += 8) {
        int i  = i0 + r;
        int dh = i >> 8, x = i & 255;
        float qv = qbase[(size_t)dh * S_ + x * 32 + lane];
        float s0 = 0.f, s1 = 0.f;
#pragma unroll
        for (int y = 0; y < 32; ++y) {
            float qy = __shfl_sync(0xffffffffu, qv, y);
            s0 = fmaf(qy, k2s[lane * 33 + y], s0);
            s1 = fmaf(qy, k2s[(lane + 32) * 33 + y], s1);
        }
        float m = fmaxf(s0, s1);
#pragma unroll
        for (int o = 16; o > 0; o >>= 1) m = fmaxf(m, __shfl_xor_sync(0xffffffffu, m, o));
        float p0 = expf(s0 - m), p1 = expf(s1 - m);
        float sum = p0 + p1;
#pragma unroll
        for (int o = 16; o > 0; o >>= 1) sum += __shfl_xor_sync(0xffffffffu, sum, o);
        float inv = 1.f / sum;
        p0 *= inv; p1 *= inv;
        float o = 0.f;
#pragma unroll
        for (int j = 0; j < 32; ++j) {
            float pj = __shfl_sync(0xffffffffu, p0, j);
            o = fmaf(pj, v2s[j * 33 + lane], o);
        }
#pragma unroll
        for (int j = 0; j < 32; ++j) {
            float pj = __shfl_sync(0xffffffffu, p1, j);
            o = fmaf(pj, v2s[(j + 32) * 33 + lane], o);
        }
        tile[r * 33 + lane] = o;
    }
    __syncthreads();
    for (int e = t; e < 1024; e += 256) {
        int d = e >> 5, rr = e & 31;
        outimg[((size_t)b * 256 + head * 32 + d) * S_ + i0 + rr] = tile[rr * 33 + d];
    }
}

// ---------------- depthwise 3x3, SAME, per-channel ----------------
__global__ void dwconv_kernel(const float* __restrict__ in, const float* __restrict__ wgt,
                              const float* __restrict__ bias, float* __restrict__ out, int Cch) {
    int idx = blockIdx.x * blockDim.x + threadIdx.x;
    int s = idx & (S_ - 1);
    int c = (idx >> 13) % Cch;
    int b = idx / (Cch * S_);
    int h = s >> 5, wv = s & 31;
    const float* p  = in + ((size_t)b * Cch + c) * S_;
    const float* wp = wgt + c * 9;
    float acc = bias[c];
#pragma unroll
    for (int dy = -1; dy <= 1; ++dy) {
        int h2 = h + dy;
        if (h2 < 0 || h2 >= H_) continue;
#pragma unroll
        for (int dx = -1; dx <= 1; ++dx) {
            int w2 = wv + dx;
            if (w2 < 0 || w2 >= W_) continue;
            acc = fmaf(wp[(dy + 1) * 3 + (dx + 1)], p[h2 * 32 + w2], acc);
        }
    }
    out[idx] = acc;
}

// ---------------- instance-norm row stats (per (b,c) over S) ----------------
__global__ void rowstats_kernel(const float* __restrict__ v,
                                float* __restrict__ mean, float* __restrict__ rstd) {
    int row = blockIdx.x;
    const float* p = v + (size_t)row * S_;
    int t = threadIdx.x;
    float sum = 0.f, sq = 0.f;
    for (int i = t; i < S_; i += 256) { float x = p[i]; sum += x; sq += x * x; }
    __shared__ float s1[256], s2[256];
    s1[t] = sum; s2[t] = sq; __syncthreads();
    for (int o = 128; o > 0; o >>= 1) {
        if (t < o) { s1[t] += s1[t + o]; s2[t] += s2[t + o]; }
        __syncthreads();
    }
    if (t == 0) {
        float m = s1[0] * (1.f / S_);
        float var = s2[0] * (1.f / S_) - m * m;
        mean[row] = m; rstd[row] = rsqrtf(var + EPSn);
    }
}

// MODE 0: gelu(norm);  MODE 1: addsrc + gelu(norm);  MODE 2: norm only
template<int MODE>
__global__ void inorm_apply_kernel(const float* __restrict__ src, const float* __restrict__ addsrc,
                                   const float* __restrict__ mean, const float* __restrict__ rstd,
                                   float* __restrict__ dst) {
    int idx = blockIdx.x * blockDim.x + threadIdx.x;
    int row = idx >> 13;
    float x = (src[idx] - mean[row]) * rstd[row];
    if (MODE <= 1) x = 0.5f * x * (1.f + erff(x * 0.7071067811865475f));
    if (MODE == 1) x += addsrc[idx];
    dst[idx] = x;
}

// ---------------- host orchestration ----------------
extern "C" void kernel_launch(void* const* d_in, const int* in_sizes, int n_in,
                              void* d_out, int out_size) {
    const float* x      = (const float*)d_in[0];
    const float* cg     = (const float*)d_in[1];
    const float* cb     = (const float*)d_in[2];
    const float* w_qkv  = (const float*)d_in[3];
    const float* w_out  = (const float*)d_in[4];
    const float* b_out  = (const float*)d_in[5];
    const float* w_dw   = (const float*)d_in[6];
    const float* b_dw   = (const float*)d_in[7];
    const float* w_comb = (const float*)d_in[8];
    const float* b_comb = (const float*)d_in[9];
    const float* w_ff1  = (const float*)d_in[10];
    const float* b_ff1  = (const float*)d_in[11];
    const float* w_ffdw = (const float*)d_in[12];
    const float* b_ffdw = (const float*)d_in[13];
    const float* w_ff2  = (const float*)d_in[14];
    const float* b_ff2  = (const float*)d_in[15];
    float* out = (float*)d_out;

    float *qkv, *bufa, *bufb, *bufc, *ff1, *ffdw;
    float *cmean, *crstd, *rmean, *rrstd, *qpart, *ksumH, *k2, *v2;
    void* p;
    cudaGetSymbolAddress(&p, g_qkv);    qkv    = (float*)p;
    cudaGetSymbolAddress(&p, g_bufa);   bufa   = (float*)p;
    cudaGetSymbolAddress(&p, g_bufb);   bufb   = (float*)p;
    cudaGetSymbolAddress(&p, g_bufc);   bufc   = (float*)p;
    cudaGetSymbolAddress(&p, g_ff1);    ff1    = (float*)p;
    cudaGetSymbolAddress(&p, g_ffdw);   ffdw   = (float*)p;
    cudaGetSymbolAddress(&p, g_cmean);  cmean  = (float*)p;
    cudaGetSymbolAddress(&p, g_crstd);  crstd  = (float*)p;
    cudaGetSymbolAddress(&p, g_rmean);  rmean  = (float*)p;
    cudaGetSymbolAddress(&p, g_rrstd);  rrstd  = (float*)p;
    cudaGetSymbolAddress(&p, g_qpart);  qpart  = (float*)p;
    cudaGetSymbolAddress(&p, g_ksumH);  ksumH  = (float*)p;
    cudaGetSymbolAddress(&p, g_k2);     k2     = (float*)p;
    cudaGetSymbolAddress(&p, g_v2);     v2     = (float*)p;

    // 1) channel layernorm stats
    cln_stats_kernel<<<Bn * S_ / 256, 256>>>(x, cmean, crstd);

    // 2) qkv = conv1x1(CLN(x), w_qkv)
    gemm_tf32_kernel<1, false><<<dim3(S_ / 128, 768 / 128, Bn), 256>>>(
        x, nullptr, w_qkv, nullptr, nullptr, cmean, crstd, cg, cb, qkv, 256, 768);

    // 3) L2-normalize q and k rows
    l2norm_kernel<<<(Bn * 512 * H_) / 8, 256>>>(qkv);

    // 4) probe partials + key reductions
    qprobe_kernel<<<BHn * 8, 256>>>(qkv, qpart);
    ksumh_kernel<<<(BHn * 32 * 32) / 256, 256>>>(qkv, ksumH);

    // 5) top-k selection + gather
    select_kernel<<<BHn, 256>>>(qkv, qpart, ksumH, k2, v2);

    // 6) attention -> o image (bufc)
    attn_kernel<<<dim3(S_ / 32, BHn), 256>>>(qkv, k2, v2, bufc);

    // 7) attn branch: conv1x1(o, w_out) + b_out -> bufa
    gemm_tf32_kernel<0, false><<<dim3(S_ / 128, 256 / 128, Bn), 256>>>(
        bufc, nullptr, w_out, b_out, nullptr, nullptr, nullptr, nullptr, nullptr, bufa, 256, 256);

    // 8) conv branch: depthwise 3x3 on x -> bufb
    dwconv_kernel<<<(Bn * Cn * S_) / 256, 256>>>(x, w_dw, b_dw, bufb, Cn);

    // 9) combine: conv1x1(concat(bufa,bufb), w_comb) + b_comb + x -> bufc
    gemm_tf32_kernel<2, true><<<dim3(S_ / 128, 256 / 128, Bn), 256>>>(
        bufa, bufb, w_comb, b_comb, x, nullptr, nullptr, nullptr, nullptr, bufc, 512, 256);

    // 10) ff1: conv1x1 -> instance norm -> gelu (in-place)
    gemm_tf32_kernel<0, false><<<dim3(S_ / 128, FFn / 128, Bn), 256>>>(
        bufc, nullptr, w_ff1, b_ff1, nullptr, nullptr, nullptr, nullptr, nullptr, ff1, 256, FFn);
    rowstats_kernel<<<Bn * FFn, 256>>>(ff1, rmean, rrstd);
    inorm_apply_kernel<0><<<(Bn * FFn * S_) / 256, 256>>>(ff1, nullptr, rmean, rrstd, ff1);

    // 11) ff depthwise: h2 = h1 + gelu(inorm(dw3x3(h1))) -> ffdw
    dwconv_kernel<<<(Bn * FFn * S_) / 256, 256>>>(ff1, w_ffdw, b_ffdw, ffdw, FFn);
    rowstats_kernel<<<Bn * FFn, 256>>>(ffdw, rmean, rrstd);
    inorm_apply_kernel<1><<<(Bn * FFn * S_) / 256, 256>>>(ffdw, ff1, rmean, rrstd, ffdw);

    // 12) ff2: conv1x1 -> instance norm -> d_out
    gemm_tf32_kernel<0, false><<<dim3(S_ / 128, 256 / 128, Bn), 256>>>(
        ffdw, nullptr, w_ff2, b_ff2, nullptr, nullptr, nullptr, nullptr, nullptr, bufc, FFn, 256);
    rowstats_kernel<<<Bn * Cn, 256>>>(bufc, rmean, rrstd);
    inorm_apply_kernel<2><<<(Bn * Cn * S_) / 256, 256>>>(bufc, nullptr, rmean, rrstd, out);
}

// round 5
// speedup vs baseline: 1.7946x; 1.3198x over previous
#include <cuda_runtime.h>
#include <math.h>
#include <stdint.h>

// ---------------- problem constants ----------------
constexpr int Bn    = 8;
constexpr int Cn    = 256;
constexpr int H_    = 256;
constexpr int W_    = 32;
constexpr int S_    = H_ * W_;      // 8192
constexpr int HEADS = 8;
constexpr int BHn   = Bn * HEADS;   // 64
constexpr int FFn   = 1024;
constexpr float EPSn = 1e-5f;

// ---------------- scratch (device globals; no runtime alloc) ----------------
__device__ float g_qkv [Bn * 768 * S_];
__device__ float g_bufa[Bn * Cn  * S_];
__device__ float g_bufb[Bn * Cn  * S_];
__device__ float g_bufc[Bn * Cn  * S_];
__device__ float g_ff1 [Bn * FFn * S_];
__device__ float g_ffdw[Bn * FFn * S_];
__device__ float g_cmean[Bn * S_];
__device__ float g_crstd[Bn * S_];
__device__ float g_qpart[BHn * 8 * 32];
__device__ float g_ksumH [BHn * 32 * 32];
__device__ float g_k2[BHn * 64 * 32];
__device__ float g_v2[BHn * 64 * 32];

// ---------------- helpers ----------------
__device__ __forceinline__ float to_tf32(float x) {
    uint32_t u;
    asm("cvt.rna.tf32.f32 %0, %1;" : "=r"(u) : "f"(x));
    return __uint_as_float(u);
}

__device__ __forceinline__ void mma_tf32(float* d, const uint32_t* a, const uint32_t* bm) {
    asm volatile(
        "mma.sync.aligned.m16n8k8.row.col.f32.tf32.tf32.f32 "
        "{%0,%1,%2,%3}, {%4,%5,%6,%7}, {%8,%9}, {%0,%1,%2,%3};"
        : "+f"(d[0]), "+f"(d[1]), "+f"(d[2]), "+f"(d[3])
        : "r"(a[0]), "r"(a[1]), "r"(a[2]), "r"(a[3]), "r"(bm[0]), "r"(bm[1]));
}

__device__ __forceinline__ float gelu_f(float x) {
    return 0.5f * x * (1.f + erff(x * 0.7071067811865475f));
}

// ---------------- channel layernorm stats (over C for each (b,s)) ----------------
__global__ void cln_stats_kernel(const float* __restrict__ x,
                                 float* __restrict__ mean, float* __restrict__ rstd) {
    int b = blockIdx.x / (S_ / 256);
    int s = (blockIdx.x % (S_ / 256)) * 256 + threadIdx.x;
    const float* p = x + (size_t)b * Cn * S_ + s;
    float sum = 0.f, sq = 0.f;
#pragma unroll 4
    for (int c = 0; c < Cn; ++c) {
        float v = p[(size_t)c * S_];
        sum += v; sq += v * v;
    }
    float m = sum * (1.f / Cn);
    float var = sq * (1.f / Cn) - m * m;
    mean[b * S_ + s] = m;
    rstd[b * S_ + s] = rsqrtf(var + EPSn);
}

// ---------------- tf32 tensor-core GEMM (double-buffered) ----------------
// Out[b,n,s] = sum_k W[n,k]*A[b,k,s]
// MODE 0: plain A0;  MODE 1: channel-LN transform of A0 on load;  MODE 2: concat(A0,A1) on k
template<int MODE, bool RES>
__global__ __launch_bounds__(256) void gemm_tf32_kernel(
    const float* __restrict__ A0, const float* __restrict__ A1,
    const float* __restrict__ Wt, const float* __restrict__ bias,
    const float* __restrict__ resid,
    const float* __restrict__ cmean, const float* __restrict__ crstd,
    const float* __restrict__ gamma, const float* __restrict__ beta,
    float* __restrict__ Out, int K, int N)
{
    __shared__ float Ws[2][16 * 132];   // [buf][k][n]
    __shared__ float As[2][16 * 132];   // [buf][k][s]
    const int b  = blockIdx.z;
    const int s0 = blockIdx.x * 128;
    const int n0 = blockIdx.y * 128;
    const int t  = threadIdx.x;
    const int lane = t & 31, warp = t >> 5;
    const int wn = warp & 3, ws = warp >> 2;
    const int n0w = wn * 32, s0w = ws * 64;
    const int r = lane >> 2, c = lane & 3;

    float acc[2][8][4];
#pragma unroll
    for (int mt = 0; mt < 2; ++mt)
#pragma unroll
        for (int nt = 0; nt < 8; ++nt)
#pragma unroll
            for (int q = 0; q < 4; ++q) acc[mt][nt][q] = 0.f;

    const int wkq = (t & 3) * 4;
    const int wnl = t >> 2;
    const int asl = (t & 31) * 4;
    const int akl = t >> 5;

    // hoisted CLN per-column factors (MODE 1 only)
    float4 m4, r4;
    if (MODE == 1) {
        m4 = *reinterpret_cast<const float4*>(cmean + (size_t)b * S_ + s0 + asl);
        r4 = *reinterpret_cast<const float4*>(crstd + (size_t)b * S_ + s0 + asl);
    }

    float4 wreg[2], areg[2];
    float  gA[2], bA[2];

    auto load_tile = [&](int k0) {
#pragma unroll
        for (int pass = 0; pass < 2; ++pass) {
            int n = wnl + pass * 64;
            wreg[pass] = *reinterpret_cast<const float4*>(Wt + (size_t)(n0 + n) * K + k0 + wkq);
        }
#pragma unroll
        for (int pass = 0; pass < 2; ++pass) {
            int k  = akl + pass * 8;
            int kg = k0 + k;
            if (MODE == 2) {
                const float* src = (kg < 256)
                    ? (A0 + ((size_t)b * 256 + kg) * S_)
                    : (A1 + ((size_t)b * 256 + (kg - 256)) * S_);
                areg[pass] = *reinterpret_cast<const float4*>(src + s0 + asl);
            } else {
                areg[pass] = *reinterpret_cast<const float4*>(A0 + ((size_t)b * K + kg) * S_ + s0 + asl);
            }
            if (MODE == 1) { gA[pass] = gamma[kg]; bA[pass] = beta[kg]; }
        }
    };

    auto sts_tile = [&](int bi) {
#pragma unroll
        for (int pass = 0; pass < 2; ++pass) {
            int n = wnl + pass * 64;
            float4 w4 = wreg[pass];
            Ws[bi][(wkq + 0) * 132 + n] = to_tf32(w4.x);
            Ws[bi][(wkq + 1) * 132 + n] = to_tf32(w4.y);
            Ws[bi][(wkq + 2) * 132 + n] = to_tf32(w4.z);
            Ws[bi][(wkq + 3) * 132 + n] = to_tf32(w4.w);
        }
#pragma unroll
        for (int pass = 0; pass < 2; ++pass) {
            int k = akl + pass * 8;
            float4 a4 = areg[pass];
            if (MODE == 1) {
                float g = gA[pass], be = bA[pass];
                a4.x = (a4.x - m4.x) * r4.x * g + be;
                a4.y = (a4.y - m4.y) * r4.y * g + be;
                a4.z = (a4.z - m4.z) * r4.z * g + be;
                a4.w = (a4.w - m4.w) * r4.w * g + be;
            }
            As[bi][k * 132 + asl + 0] = to_tf32(a4.x);
            As[bi][k * 132 + asl + 1] = to_tf32(a4.y);
            As[bi][k * 132 + asl + 2] = to_tf32(a4.z);
            As[bi][k * 132 + asl + 3] = to_tf32(a4.w);
        }
    };

    auto compute = [&](int bi) {
#pragma unroll
        for (int kk = 0; kk < 16; kk += 8) {
            uint32_t af[2][4];
#pragma unroll
            for (int mt = 0; mt < 2; ++mt) {
                int row = n0w + mt * 16 + r;
                af[mt][0] = __float_as_uint(Ws[bi][(kk + c) * 132 + row]);
                af[mt][1] = __float_as_uint(Ws[bi][(kk + c) * 132 + row + 8]);
                af[mt][2] = __float_as_uint(Ws[bi][(kk + c + 4) * 132 + row]);
                af[mt][3] = __float_as_uint(Ws[bi][(kk + c + 4) * 132 + row + 8]);
            }
            uint32_t bf[8][2];
#pragma unroll
            for (int nt = 0; nt < 8; ++nt) {
                int col = s0w + nt * 8 + r;
                bf[nt][0] = __float_as_uint(As[bi][(kk + c) * 132 + col]);
                bf[nt][1] = __float_as_uint(As[bi][(kk + c + 4) * 132 + col]);
            }
#pragma unroll
            for (int mt = 0; mt < 2; ++mt)
#pragma unroll
                for (int nt = 0; nt < 8; ++nt)
                    mma_tf32(acc[mt][nt], af[mt], bf[nt]);
        }
    };

    const int nt_iters = K / 16;
    load_tile(0);
    sts_tile(0);
    __syncthreads();
    for (int it = 1; it < nt_iters; ++it) {
        load_tile(it * 16);          // LDG overlaps compute below
        compute((it - 1) & 1);
        sts_tile(it & 1);
        __syncthreads();
    }
    compute((nt_iters - 1) & 1);

    // epilogue
#pragma unroll
    for (int mt = 0; mt < 2; ++mt) {
#pragma unroll
        for (int half = 0; half < 2; ++half) {
            int n = n0 + n0w + mt * 16 + r + half * 8;
            float bv = (bias != nullptr) ? bias[n] : 0.f;
            float* orow = Out + ((size_t)b * N + n) * S_;
            const float* rrow = RES ? (resid + ((size_t)b * N + n) * S_) : nullptr;
#pragma unroll
            for (int nt = 0; nt < 8; ++nt) {
                int s = s0 + s0w + nt * 8 + 2 * c;
                float2 o;
                o.x = acc[mt][nt][half * 2 + 0] + bv;
                o.y = acc[mt][nt][half * 2 + 1] + bv;
                if (RES) {
                    float2 rv = *reinterpret_cast<const float2*>(rrow + s);
                    o.x += rv.x; o.y += rv.y;
                }
                *reinterpret_cast<float2*>(orow + s) = o;
            }
        }
    }
}

// ---------------- L2 normalize q and k rows over W (32 contiguous) ----------------
__global__ void l2norm_kernel(float* __restrict__ qkv) {
    int gw   = (blockIdx.x * blockDim.x + threadIdx.x) >> 5;
    int lane = threadIdx.x & 31;
    int x  = gw % H_;
    int ch = (gw / H_) % 512;
    int b  = gw / (H_ * 512);
    float* p = qkv + ((size_t)b * 768 + ch) * S_ + x * W_ + lane;
    float v = *p;
    float sq = v * v;
#pragma unroll
    for (int o = 16; o > 0; o >>= 1) sq += __shfl_xor_sync(0xffffffffu, sq, o);
    float nrm = fmaxf(sqrtf(sq), 1e-12f);
    *p = v / nrm;
}

// ---------------- q_probe partials ----------------
__global__ void qprobe_kernel(const float* __restrict__ qkv, float* __restrict__ qpart) {
    int bp = blockIdx.x;
    int bh = bp >> 3, part = bp & 7;
    int b = bh >> 3, head = bh & 7;
    int t = threadIdx.x, y = t & 31, sub = t >> 5;
    const float* base = qkv + ((size_t)b * 768 + head * 32) * S_;
    float acc = 0.f;
    for (int rr = sub * 128; rr < sub * 128 + 128; ++rr) {
        int dh = rr >> 5;
        int x  = part * 32 + (rr & 31);
        acc += base[(size_t)dh * S_ + x * 32 + y];
    }
    __shared__ float sh[256];
    sh[t] = acc;
    __syncthreads();
    if (t < 32) {
        float s = 0.f;
#pragma unroll
        for (int p = 0; p < 8; ++p) s += sh[p * 32 + t];
        qpart[bp * 32 + t] = s;
    }
}

// ---------------- ksumH[bh,dh,y] = sum_x kn ----------------
__global__ void ksumh_kernel(const float* __restrict__ qkv, float* __restrict__ ksumH) {
    int idx = blockIdx.x * blockDim.x + threadIdx.x;
    int y = idx & 31, dh = (idx >> 5) & 31, bh = idx >> 10;
    int b = bh >> 3, head = bh & 7;
    const float* p = qkv + ((size_t)b * 768 + 256 + head * 32 + dh) * S_ + y;
    float s = 0.f;
    for (int x = 0; x < H_; ++x) s += p[x * 32];
    ksumH[idx] = s;
}

// ---------------- top-k selection + gather ----------------
__global__ void select_kernel(const float* __restrict__ qkv,
                              const float* __restrict__ qpart,
                              const float* __restrict__ ksumH,
                              float* __restrict__ k2, float* __restrict__ v2) {
    int bh = blockIdx.x; int b = bh >> 3, head = bh & 7;
    int t = threadIdx.x;
    __shared__ float qp[32];
    __shared__ float shs[32];
    __shared__ int   ih[8];
    __shared__ float sws[256];
    __shared__ int   iw[8];

    if (t < 32) {
        float s = 0.f;
#pragma unroll
        for (int p = 0; p < 8; ++p) s += qpart[(bh * 8 + p) * 32 + t];
        qp[t] = s;
    }
    __syncthreads();
    if (t < 32) {
        float s = 0.f;
        const float* kr = ksumH + (bh * 32 + t) * 32;
#pragma unroll
        for (int y = 0; y < 32; ++y) s += qp[y] * kr[y];
        shs[t] = s;
    }
    __syncthreads();
    if (t == 0) {
        for (int j = 0; j < 8; ++j) {
            float best = -INFINITY; int bi = 0;
            for (int i = 0; i < 32; ++i)
                if (shs[i] > best) { best = shs[i]; bi = i; }
            ih[j] = bi; shs[bi] = -INFINITY;
        }
    }
    __syncthreads();
    {
        int x = t;
        float s = 0.f;
        const float* kbase = qkv + ((size_t)b * 768 + 256 + head * 32) * S_ + x * 32;
        for (int j = 0; j < 8; ++j) {
            const float* kp = kbase + (size_t)ih[j] * S_;
#pragma unroll
            for (int y = 0; y < 32; ++y) s += kp[y] * qp[y];
        }
        sws[x] = s;
    }
    __syncthreads();
    if (t == 0) {
        for (int j = 0; j < 8; ++j) {
            float best = -INFINITY; int bi = 0;
            for (int i = 0; i < 256; ++i)
                if (sws[i] > best) { best = sws[i]; bi = i; }
            iw[j] = bi; sws[bi] = -INFINITY;
        }
    }
    __syncthreads();
    for (int e = t; e < 64 * 32; e += 256) {
        int j = e >> 5, y = e & 31;
        int dh = ih[j >> 3], x = iw[j & 7];
        size_t koff = ((size_t)b * 768 + 256 + head * 32 + dh) * S_ + x * 32 + y;
        k2[(bh * 64 + j) * 32 + y] = qkv[koff];
        v2[(bh * 64 + j) * 32 + y] = qkv[koff + (size_t)256 * S_];
    }
}

// ---------------- attention: 8192 rows x 64 keys per bh ----------------
__global__ __launch_bounds__(256) void attn_kernel(const float* __restrict__ qkv,
                                                   const float* __restrict__ k2g,
                                                   const float* __restrict__ v2g,
                                                   float* __restrict__ outimg) {
    int bh = blockIdx.y; int b = bh >> 3, head = bh & 7;
    int i0 = blockIdx.x * 32;
    int t = threadIdx.x, w = t >> 5, lane = t & 31;
    __shared__ float k2s[64 * 33];
    __shared__ float v2s[64 * 33];
    __shared__ float tile[32 * 33];
    for (int e = t; e < 64 * 32; e += 256) {
        int j = e >> 5, y = e & 31;
        k2s[j * 33 + y] = k2g[(bh * 64 + j) * 32 + y];
        v2s[j * 33 + y] = v2g[(bh * 64 + j) * 32 + y];
    }
    __syncthreads();
    const float* qbase = qkv + ((size_t)b * 768 + head * 32) * S_;
    for (int r = w; r < 32; r += 8) {
        int i  = i0 + r;
        int dh = i >> 8, x = i & 255;
        float qv = qbase[(size_t)dh * S_ + x * 32 + lane];
        float s0 = 0.f, s1 = 0.f;
#pragma unroll
        for (int y = 0; y < 32; ++y) {
            float qy = __shfl_sync(0xffffffffu, qv, y);
            s0 = fmaf(qy, k2s[lane * 33 + y], s0);
            s1 = fmaf(qy, k2s[(lane + 32) * 33 + y], s1);
        }
        float m = fmaxf(s0, s1);
#pragma unroll
        for (int o = 16; o > 0; o >>= 1) m = fmaxf(m, __shfl_xor_sync(0xffffffffu, m, o));
        float p0 = expf(s0 - m), p1 = expf(s1 - m);
        float sum = p0 + p1;
#pragma unroll
        for (int o = 16; o > 0; o >>= 1) sum += __shfl_xor_sync(0xffffffffu, sum, o);
        float inv = 1.f / sum;
        p0 *= inv; p1 *= inv;
        float o = 0.f;
#pragma unroll
        for (int j = 0; j < 32; ++j) {
            float pj = __shfl_sync(0xffffffffu, p0, j);
            o = fmaf(pj, v2s[j * 33 + lane], o);
        }
#pragma unroll
        for (int j = 0; j < 32; ++j) {
            float pj = __shfl_sync(0xffffffffu, p1, j);
            o = fmaf(pj, v2s[(j + 32) * 33 + lane], o);
        }
        tile[r * 33 + lane] = o;
    }
    __syncthreads();
    for (int e = t; e < 1024; e += 256) {
        int d = e >> 5, rr = e & 31;
        outimg[((size_t)b * 256 + head * 32 + d) * S_ + i0 + rr] = tile[rr * 33 + d];
    }
}

// ---------------- depthwise 3x3 on x (SAME), simple ----------------
__global__ void dwconv_kernel(const float* __restrict__ in, const float* __restrict__ wgt,
                              const float* __restrict__ bias, float* __restrict__ out, int Cch) {
    int idx = blockIdx.x * blockDim.x + threadIdx.x;
    int s = idx & (S_ - 1);
    int c = (idx >> 13) % Cch;
    int b = idx / (Cch * S_);
    int h = s >> 5, wv = s & 31;
    const float* p  = in + ((size_t)b * Cch + c) * S_;
    const float* wp = wgt + c * 9;
    float acc = bias[c];
#pragma unroll
    for (int dy = -1; dy <= 1; ++dy) {
        int h2 = h + dy;
        if (h2 < 0 || h2 >= H_) continue;
#pragma unroll
        for (int dx = -1; dx <= 1; ++dx) {
            int w2 = wv + dx;
            if (w2 < 0 || w2 >= W_) continue;
            acc = fmaf(wp[(dy + 1) * 3 + (dx + 1)], p[h2 * 32 + w2], acc);
        }
    }
    out[idx] = acc;
}

// ---------------- fused FF middle: h2 = g1 + gelu(inorm(dw3x3(g1))), g1=gelu(inorm(ff1)) ----
// One block per (b,c) row: whole 256x32 image lives in smem.
__global__ __launch_bounds__(256) void ff_middle_kernel(
    const float* __restrict__ ff1raw, const float* __restrict__ wgt,
    const float* __restrict__ bias, float* __restrict__ h2out)
{
    __shared__ float img[S_];
    __shared__ float red1[256], red2[256];
    const int row = blockIdx.x;                  // b*FFn + c
    const int c   = row & (FFn - 1);
    const int t   = threadIdx.x;
    const float* src = ff1raw + (size_t)row * S_;
    float* dst = h2out + (size_t)row * S_;

    // stage 1: load raw row + stats
    float sum = 0.f, sq = 0.f;
#pragma unroll
    for (int k = 0; k < 8; ++k) {
        float4 v = reinterpret_cast<const float4*>(src)[t + k * 256];
        reinterpret_cast<float4*>(img)[t + k * 256] = v;
        sum += v.x + v.y + v.z + v.w;
        sq  += v.x * v.x + v.y * v.y + v.z * v.z + v.w * v.w;
    }
    red1[t] = sum; red2[t] = sq; __syncthreads();
    for (int o = 128; o > 0; o >>= 1) {
        if (t < o) { red1[t] += red1[t + o]; red2[t] += red2[t + o]; }
        __syncthreads();
    }
    float m1 = red1[0] * (1.f / S_);
    float rs1 = rsqrtf(red2[0] * (1.f / S_) - m1 * m1 + EPSn);

    // stage 2: transform own elements to g1 = gelu(norm)
#pragma unroll
    for (int k = 0; k < 8; ++k) {
        float4 v = reinterpret_cast<float4*>(img)[t + k * 256];
        v.x = gelu_f((v.x - m1) * rs1);
        v.y = gelu_f((v.y - m1) * rs1);
        v.z = gelu_f((v.z - m1) * rs1);
        v.w = gelu_f((v.w - m1) * rs1);
        reinterpret_cast<float4*>(img)[t + k * 256] = v;
    }
    __syncthreads();

    // stage 3: depthwise 3x3 from smem; 32 outputs/thread in regs + stats
    float wp[9];
#pragma unroll
    for (int j = 0; j < 9; ++j) wp[j] = wgt[c * 9 + j];
    float bv = bias[c];
    float o[32];
    float sum2 = 0.f, sq2 = 0.f;
#pragma unroll
    for (int k = 0; k < 32; ++k) {
        int idx = t + k * 256;
        int h = idx >> 5, wv = idx & 31;
        float acc = bv;
#pragma unroll
        for (int dy = -1; dy <= 1; ++dy) {
            int h2 = h + dy;
            if (h2 < 0 || h2 >= H_) continue;
#pragma unroll
            for (int dx = -1; dx <= 1; ++dx) {
                int w2 = wv + dx;
                if (w2 < 0 || w2 >= W_) continue;
                acc = fmaf(wp[(dy + 1) * 3 + (dx + 1)], img[h2 * 32 + w2], acc);
            }
        }
        o[k] = acc; sum2 += acc; sq2 += acc * acc;
    }
    __syncthreads();   // protect red arrays before reuse
    red1[t] = sum2; red2[t] = sq2; __syncthreads();
    for (int oo = 128; oo > 0; oo >>= 1) {
        if (t < oo) { red1[t] += red1[t + oo]; red2[t] += red2[t + oo]; }
        __syncthreads();
    }
    float m2 = red1[0] * (1.f / S_);
    float rs2 = rsqrtf(red2[0] * (1.f / S_) - m2 * m2 + EPSn);

    // stage 4: h2 = g1 + gelu(norm(o))
#pragma unroll
    for (int k = 0; k < 32; ++k) {
        int idx = t + k * 256;
        dst[idx] = img[idx] + gelu_f((o[k] - m2) * rs2);
    }
}

// ---------------- fused final instance norm: out = inorm(row) ----------------
__global__ __launch_bounds__(256) void final_norm_kernel(
    const float* __restrict__ src, float* __restrict__ dst)
{
    __shared__ float red1[256], red2[256];
    const int row = blockIdx.x;
    const int t = threadIdx.x;
    const float4* s4 = reinterpret_cast<const float4*>(src + (size_t)row * S_);
    float4* d4 = reinterpret_cast<float4*>(dst + (size_t)row * S_);
    float4 loc[8];
    float sum = 0.f, sq = 0.f;
#pragma unroll
    for (int k = 0; k < 8; ++k) {
        float4 v = s4[t + k * 256];
        loc[k] = v;
        sum += v.x + v.y + v.z + v.w;
        sq  += v.x * v.x + v.y * v.y + v.z * v.z + v.w * v.w;
    }
    red1[t] = sum; red2[t] = sq; __syncthreads();
    for (int o = 128; o > 0; o >>= 1) {
        if (t < o) { red1[t] += red1[t + o]; red2[t] += red2[t + o]; }
        __syncthreads();
    }
    float m = red1[0] * (1.f / S_);
    float rs = rsqrtf(red2[0] * (1.f / S_) - m * m + EPSn);
#pragma unroll
    for (int k = 0; k < 8; ++k) {
        float4 v = loc[k];
        v.x = (v.x - m) * rs; v.y = (v.y - m) * rs;
        v.z = (v.z - m) * rs; v.w = (v.w - m) * rs;
        d4[t + k * 256] = v;
    }
}

// ---------------- host orchestration ----------------
extern "C" void kernel_launch(void* const* d_in, const int* in_sizes, int n_in,
                              void* d_out, int out_size) {
    const float* x      = (const float*)d_in[0];
    const float* cg     = (const float*)d_in[1];
    const float* cb     = (const float*)d_in[2];
    const float* w_qkv  = (const float*)d_in[3];
    const float* w_out  = (const float*)d_in[4];
    const float* b_out  = (const float*)d_in[5];
    const float* w_dw   = (const float*)d_in[6];
    const float* b_dw   = (const float*)d_in[7];
    const float* w_comb = (const float*)d_in[8];
    const float* b_comb = (const float*)d_in[9];
    const float* w_ff1  = (const float*)d_in[10];
    const float* b_ff1  = (const float*)d_in[11];
    const float* w_ffdw = (const float*)d_in[12];
    const float* b_ffdw = (const float*)d_in[13];
    const float* w_ff2  = (const float*)d_in[14];
    const float* b_ff2  = (const float*)d_in[15];
    float* out = (float*)d_out;

    float *qkv, *bufa, *bufb, *bufc, *ff1, *ffdw;
    float *cmean, *crstd, *qpart, *ksumH, *k2, *v2;
    void* p;
    cudaGetSymbolAddress(&p, g_qkv);    qkv    = (float*)p;
    cudaGetSymbolAddress(&p, g_bufa);   bufa   = (float*)p;
    cudaGetSymbolAddress(&p, g_bufb);   bufb   = (float*)p;
    cudaGetSymbolAddress(&p, g_bufc);   bufc   = (float*)p;
    cudaGetSymbolAddress(&p, g_ff1);    ff1    = (float*)p;
    cudaGetSymbolAddress(&p, g_ffdw);   ffdw   = (float*)p;
    cudaGetSymbolAddress(&p, g_cmean);  cmean  = (float*)p;
    cudaGetSymbolAddress(&p, g_crstd);  crstd  = (float*)p;
    cudaGetSymbolAddress(&p, g_qpart);  qpart  = (float*)p;
    cudaGetSymbolAddress(&p, g_ksumH);  ksumH  = (float*)p;
    cudaGetSymbolAddress(&p, g_k2);     k2     = (float*)p;
    cudaGetSymbolAddress(&p, g_v2);     v2     = (float*)p;

    // 1) channel layernorm stats
    cln_stats_kernel<<<Bn * S_ / 256, 256>>>(x, cmean, crstd);

    // 2) qkv = conv1x1(CLN(x), w_qkv)
    gemm_tf32_kernel<1, false><<<dim3(S_ / 128, 768 / 128, Bn), 256>>>(
        x, nullptr, w_qkv, nullptr, nullptr, cmean, crstd, cg, cb, qkv, 256, 768);

    // 3) L2-normalize q and k rows
    l2norm_kernel<<<(Bn * 512 * H_) / 8, 256>>>(qkv);

    // 4) probe partials + key reductions
    qprobe_kernel<<<BHn * 8, 256>>>(qkv, qpart);
    ksumh_kernel<<<(BHn * 32 * 32) / 256, 256>>>(qkv, ksumH);

    // 5) top-k selection + gather
    select_kernel<<<BHn, 256>>>(qkv, qpart, ksumH, k2, v2);

    // 6) attention -> o image (bufc)
    attn_kernel<<<dim3(S_ / 32, BHn), 256>>>(qkv, k2, v2, bufc);

    // 7) attn branch: conv1x1(o, w_out) + b_out -> bufa
    gemm_tf32_kernel<0, false><<<dim3(S_ / 128, 256 / 128, Bn), 256>>>(
        bufc, nullptr, w_out, b_out, nullptr, nullptr, nullptr, nullptr, nullptr, bufa, 256, 256);

    // 8) conv branch: depthwise 3x3 on x -> bufb
    dwconv_kernel<<<(Bn * Cn * S_) / 256, 256>>>(x, w_dw, b_dw, bufb, Cn);

    // 9) combine: conv1x1(concat(bufa,bufb), w_comb) + b_comb + x -> bufc
    gemm_tf32_kernel<2, true><<<dim3(S_ / 128, 256 / 128, Bn), 256>>>(
        bufa, bufb, w_comb, b_comb, x, nullptr, nullptr, nullptr, nullptr, bufc, 512, 256);

    // 10) ff1 raw: conv1x1 -> ff1
    gemm_tf32_kernel<0, false><<<dim3(S_ / 128, FFn / 128, Bn), 256>>>(
        bufc, nullptr, w_ff1, b_ff1, nullptr, nullptr, nullptr, nullptr, nullptr, ff1, 256, FFn);

    // 11) fused FF middle: ff1(raw) -> h2 (ffdw)
    ff_middle_kernel<<<Bn * FFn, 256>>>(ff1, w_ffdw, b_ffdw, ffdw);

    // 12) ff2: conv1x1(h2) -> bufc;  final instance norm -> out
    gemm_tf32_kernel<0, false><<<dim3(S_ / 128, 256 / 128, Bn), 256>>>(
        ffdw, nullptr, w_ff2, b_ff2, nullptr, nullptr, nullptr, nullptr, nullptr, bufc, FFn, 256);
    final_norm_kernel<<<Bn * Cn, 256>>>(bufc, out);
}

// round 7
// speedup vs baseline: 2.2280x; 1.2415x over previous
#include <cuda_runtime.h>
#include <cuda_fp16.h>
#include <math.h>
#include <stdint.h>

// ---------------- problem constants ----------------
constexpr int Bn    = 8;
constexpr int Cn    = 256;
constexpr int H_    = 256;
constexpr int W_    = 32;
constexpr int S_    = H_ * W_;      // 8192
constexpr int HEADS = 8;
constexpr int BHn   = Bn * HEADS;   // 64
constexpr int FFn   = 1024;
constexpr float EPSn = 1e-5f;

// ---------------- scratch (device globals; no runtime alloc) ----------------
__device__ float g_qkv [Bn * 768 * S_];
__device__ float g_bufa[Bn * Cn  * S_];
__device__ float g_bufb[Bn * Cn  * S_];
__device__ float g_bufc[Bn * Cn  * S_];
__device__ float g_ff1 [Bn * FFn * S_];
__device__ float g_ffdw[Bn * FFn * S_];
__device__ float g_cmean[Bn * S_];
__device__ float g_crstd[Bn * S_];
__device__ float g_qpart[BHn * 8 * 32];
__device__ float g_ksumH [BHn * 32 * 32];
__device__ float g_k2[BHn * 64 * 32];
__device__ float g_v2[BHn * 64 * 32];

// ---------------- helpers ----------------
__device__ __forceinline__ uint32_t smem_u32(const void* p) {
    return (uint32_t)__cvta_generic_to_shared(p);
}

__device__ __forceinline__ void ldsm_x4(uint32_t* r, uint32_t a) {
    asm volatile("ldmatrix.sync.aligned.m8n8.x4.shared.b16 {%0,%1,%2,%3}, [%4];"
        : "=r"(r[0]), "=r"(r[1]), "=r"(r[2]), "=r"(r[3]) : "r"(a));
}

__device__ __forceinline__ void ldsm_x4t(uint32_t* r, uint32_t a) {
    asm volatile("ldmatrix.sync.aligned.m8n8.x4.trans.shared.b16 {%0,%1,%2,%3}, [%4];"
        : "=r"(r[0]), "=r"(r[1]), "=r"(r[2]), "=r"(r[3]) : "r"(a));
}

__device__ __forceinline__ void mma_f16(float* d, const uint32_t* a, const uint32_t* b) {
    asm volatile(
        "mma.sync.aligned.m16n8k16.row.col.f32.f16.f16.f32 "
        "{%0,%1,%2,%3}, {%4,%5,%6,%7}, {%8,%9}, {%0,%1,%2,%3};"
        : "+f"(d[0]), "+f"(d[1]), "+f"(d[2]), "+f"(d[3])
        : "r"(a[0]), "r"(a[1]), "r"(a[2]), "r"(a[3]), "r"(b[0]), "r"(b[1]));
}

__device__ __forceinline__ float gelu_f(float x) {
    return 0.5f * x * (1.f + erff(x * 0.7071067811865475f));
}

// ---------------- channel layernorm stats (over C for each (b,s)) ----------------
__global__ void cln_stats_kernel(const float* __restrict__ x,
                                 float* __restrict__ mean, float* __restrict__ rstd) {
    int b = blockIdx.x / (S_ / 256);
    int s = (blockIdx.x % (S_ / 256)) * 256 + threadIdx.x;
    const float* p = x + (size_t)b * Cn * S_ + s;
    float sum = 0.f, sq = 0.f;
#pragma unroll 4
    for (int c = 0; c < Cn; ++c) {
        float v = p[(size_t)c * S_];
        sum += v; sq += v * v;
    }
    float m = sum * (1.f / Cn);
    float var = sq * (1.f / Cn) - m * m;
    mean[b * S_ + s] = m;
    rstd[b * S_ + s] = rsqrtf(var + EPSn);
}

// ---------------- fp16 tensor-core GEMM (double-buffered, ldmatrix) ----------------
// Out[b,n,s] = sum_k W[n,k]*A[b,k,s]
// MODE 0: plain A0;  MODE 1: channel-LN transform of A0 on load;  MODE 2: concat(A0,A1) on k
constexpr int WS_STR = 24;    // halves per n-row (16 + 8 pad)
constexpr int AS_STR = 136;   // halves per k-row (128 + 8 pad)

template<int MODE, bool RES>
__global__ __launch_bounds__(256) void gemm_f16_kernel(
    const float* __restrict__ A0, const float* __restrict__ A1,
    const float* __restrict__ Wt, const float* __restrict__ bias,
    const float* __restrict__ resid,
    const float* __restrict__ cmean, const float* __restrict__ crstd,
    const float* __restrict__ gamma, const float* __restrict__ beta,
    float* __restrict__ Out, int K, int N)
{
    __shared__ __align__(16) __half Ws[2][128 * WS_STR];  // [n][k]
    __shared__ __align__(16) __half As[2][16 * AS_STR];   // [k][s]
    const int b  = blockIdx.z;
    const int s0 = blockIdx.x * 128;
    const int n0 = blockIdx.y * 128;
    const int t  = threadIdx.x;
    const int lane = t & 31, warp = t >> 5;
    const int wn = warp & 3, ws = warp >> 2;
    const int n0w = wn * 32, s0w = ws * 64;
    const int r = lane >> 2, c = lane & 3;

    float acc[2][8][4];
#pragma unroll
    for (int mt = 0; mt < 2; ++mt)
#pragma unroll
        for (int nt = 0; nt < 8; ++nt)
#pragma unroll
            for (int q = 0; q < 4; ++q) acc[mt][nt][q] = 0.f;

    const int wkq = (t & 3) * 4;
    const int wnl = t >> 2;
    const int asl = (t & 31) * 4;
    const int akl = t >> 5;

    // precomputed ldmatrix lane addresses for both buffers
    uint32_t aA[2][2], aB[2][4];
#pragma unroll
    for (int bi = 0; bi < 2; ++bi) {
#pragma unroll
        for (int mt = 0; mt < 2; ++mt) {
            int row = n0w + mt * 16 + (lane & 7) + ((lane >> 3) & 1) * 8;
            int kofs = (lane >> 4) * 8;
            aA[bi][mt] = smem_u32(&Ws[bi][row * WS_STR + kofs]);
        }
#pragma unroll
        for (int ntp = 0; ntp < 4; ++ntp) {
            int k = (lane & 7) + ((lane >> 3) & 1) * 8;
            int col = s0w + (ntp * 2 + (lane >> 4)) * 8;
            aB[bi][ntp] = smem_u32(&As[bi][k * AS_STR + col]);
        }
    }

    // hoisted CLN per-column factors (MODE 1 only)
    float4 m4, r4;
    if (MODE == 1) {
        m4 = *reinterpret_cast<const float4*>(cmean + (size_t)b * S_ + s0 + asl);
        r4 = *reinterpret_cast<const float4*>(crstd + (size_t)b * S_ + s0 + asl);
    }

    float4 wreg[2], areg[2];
    float  gA[2], bA[2];

    auto load_tile = [&](int k0) {
#pragma unroll
        for (int pass = 0; pass < 2; ++pass) {
            int n = wnl + pass * 64;
            wreg[pass] = *reinterpret_cast<const float4*>(Wt + (size_t)(n0 + n) * K + k0 + wkq);
        }
#pragma unroll
        for (int pass = 0; pass < 2; ++pass) {
            int k  = akl + pass * 8;
            int kg = k0 + k;
            if (MODE == 2) {
                const float* src = (kg < 256)
                    ? (A0 + ((size_t)b * 256 + kg) * S_)
                    : (A1 + ((size_t)b * 256 + (kg - 256)) * S_);
                areg[pass] = *reinterpret_cast<const float4*>(src + s0 + asl);
            } else {
                areg[pass] = *reinterpret_cast<const float4*>(A0 + ((size_t)b * K + kg) * S_ + s0 + asl);
            }
            if (MODE == 1) { gA[pass] = gamma[kg]; bA[pass] = beta[kg]; }
        }
    };

    auto sts_tile = [&](int bi) {
#pragma unroll
        for (int pass = 0; pass < 2; ++pass) {
            int n = wnl + pass * 64;
            float4 w4 = wreg[pass];
            __half2* dst = reinterpret_cast<__half2*>(&Ws[bi][n * WS_STR + wkq]);
            dst[0] = __floats2half2_rn(w4.x, w4.y);
            dst[1] = __floats2half2_rn(w4.z, w4.w);
        }
#pragma unroll
        for (int pass = 0; pass < 2; ++pass) {
            int k = akl + pass * 8;
            float4 a4 = areg[pass];
            if (MODE == 1) {
                float g = gA[pass], be = bA[pass];
                a4.x = (a4.x - m4.x) * r4.x * g + be;
                a4.y = (a4.y - m4.y) * r4.y * g + be;
                a4.z = (a4.z - m4.z) * r4.z * g + be;
                a4.w = (a4.w - m4.w) * r4.w * g + be;
            }
            __half2* dst = reinterpret_cast<__half2*>(&As[bi][k * AS_STR + asl]);
            dst[0] = __floats2half2_rn(a4.x, a4.y);
            dst[1] = __floats2half2_rn(a4.z, a4.w);
        }
    };

    auto compute = [&](int bi) {
        uint32_t af[2][4];
        ldsm_x4(af[0], aA[bi][0]);
        ldsm_x4(af[1], aA[bi][1]);
        uint32_t bf[8][2];
#pragma unroll
        for (int ntp = 0; ntp < 4; ++ntp) {
            uint32_t rr[4];
            ldsm_x4t(rr, aB[bi][ntp]);
            bf[2 * ntp][0] = rr[0]; bf[2 * ntp][1] = rr[1];
            bf[2 * ntp + 1][0] = rr[2]; bf[2 * ntp + 1][1] = rr[3];
        }
#pragma unroll
        for (int mt = 0; mt < 2; ++mt)
#pragma unroll
            for (int nt = 0; nt < 8; ++nt)
                mma_f16(acc[mt][nt], af[mt], bf[nt]);
    };

    const int nt_iters = K / 16;
    load_tile(0);
    sts_tile(0);
    __syncthreads();
    for (int it = 1; it < nt_iters; ++it) {
        load_tile(it * 16);          // LDG overlaps compute below
        compute((it - 1) & 1);
        sts_tile(it & 1);
        __syncthreads();
    }
    compute((nt_iters - 1) & 1);

    // epilogue
#pragma unroll
    for (int mt = 0; mt < 2; ++mt) {
#pragma unroll
        for (int half = 0; half < 2; ++half) {
            int n = n0 + n0w + mt * 16 + r + half * 8;
            float bv = (bias != nullptr) ? bias[n] : 0.f;
            float* orow = Out + ((size_t)b * N + n) * S_;
            const float* rrow = RES ? (resid + ((size_t)b * N + n) * S_) : nullptr;
#pragma unroll
            for (int nt = 0; nt < 8; ++nt) {
                int s = s0 + s0w + nt * 8 + 2 * c;
                float2 o;
                o.x = acc[mt][nt][half * 2 + 0] + bv;
                o.y = acc[mt][nt][half * 2 + 1] + bv;
                if (RES) {
                    float2 rv = *reinterpret_cast<const float2*>(rrow + s);
                    o.x += rv.x; o.y += rv.y;
                }
                *reinterpret_cast<float2*>(orow + s) = o;
            }
        }
    }
}

// ---------------- L2 normalize q and k rows over W (32 contiguous) ----------------
__global__ void l2norm_kernel(float* __restrict__ qkv) {
    int gw   = (blockIdx.x * blockDim.x + threadIdx.x) >> 5;
    int lane = threadIdx.x & 31;
    int x  = gw % H_;
    int ch = (gw / H_) % 512;
    int b  = gw / (H_ * 512);
    float* p = qkv + ((size_t)b * 768 + ch) * S_ + x * W_ + lane;
    float v = *p;
    float sq = v * v;
#pragma unroll
    for (int o = 16; o > 0; o >>= 1) sq += __shfl_xor_sync(0xffffffffu, sq, o);
    float nrm = fmaxf(sqrtf(sq), 1e-12f);
    *p = v / nrm;
}

// ---------------- q_probe partials ----------------
__global__ void qprobe_kernel(const float* __restrict__ qkv, float* __restrict__ qpart) {
    int bp = blockIdx.x;
    int bh = bp >> 3, part = bp & 7;
    int b = bh >> 3, head = bh & 7;
    int t = threadIdx.x, y = t & 31, sub = t >> 5;
    const float* base = qkv + ((size_t)b * 768 + head * 32) * S_;
    float acc = 0.f;
    for (int rr = sub * 128; rr < sub * 128 + 128; ++rr) {
        int dh = rr >> 5;
        int x  = part * 32 + (rr & 31);
        acc += base[(size_t)dh * S_ + x * 32 + y];
    }
    __shared__ float sh[256];
    sh[t] = acc;
    __syncthreads();
    if (t < 32) {
        float s = 0.f;
#pragma unroll
        for (int p = 0; p < 8; ++p) s += sh[p * 32 + t];
        qpart[bp * 32 + t] = s;
    }
}

// ---------------- ksumH[bh,dh,y] = sum_x kn ----------------
__global__ void ksumh_kernel(const float* __restrict__ qkv, float* __restrict__ ksumH) {
    int idx = blockIdx.x * blockDim.x + threadIdx.x;
    int y = idx & 31, dh = (idx >> 5) & 31, bh = idx >> 10;
    int b = bh >> 3, head = bh & 7;
    const float* p = qkv + ((size_t)b * 768 + 256 + head * 32 + dh) * S_ + y;
    float s = 0.f;
    for (int x = 0; x < H_; ++x) s += p[x * 32];
    ksumH[idx] = s;
}

// ---------------- top-k selection + gather ----------------
__global__ void select_kernel(const float* __restrict__ qkv,
                              const float* __restrict__ qpart,
                              const float* __restrict__ ksumH,
                              float* __restrict__ k2, float* __restrict__ v2) {
    int bh = blockIdx.x; int b = bh >> 3, head = bh & 7;
    int t = threadIdx.x;
    __shared__ float qp[32];
    __shared__ float shs[32];
    __shared__ int   ih[8];
    __shared__ float sws[256];
    __shared__ int   iw[8];

    if (t < 32) {
        float s = 0.f;
#pragma unroll
        for (int p = 0; p < 8; ++p) s += qpart[(bh * 8 + p) * 32 + t];
        qp[t] = s;
    }
    __syncthreads();
    if (t < 32) {
        float s = 0.f;
        const float* kr = ksumH + (bh * 32 + t) * 32;
#pragma unroll
        for (int y = 0; y < 32; ++y) s += qp[y] * kr[y];
        shs[t] = s;
    }
    __syncthreads();
    if (t == 0) {
        for (int j = 0; j < 8; ++j) {
            float best = -INFINITY; int bi = 0;
            for (int i = 0; i < 32; ++i)
                if (shs[i] > best) { best = shs[i]; bi = i; }
            ih[j] = bi; shs[bi] = -INFINITY;
        }
    }
    __syncthreads();
    {
        int x = t;
        float s = 0.f;
        const float* kbase = qkv + ((size_t)b * 768 + 256 + head * 32) * S_ + x * 32;
        for (int j = 0; j < 8; ++j) {
            const float* kp = kbase + (size_t)ih[j] * S_;
#pragma unroll
            for (int y = 0; y < 32; ++y) s += kp[y] * qp[y];
        }
        sws[x] = s;
    }
    __syncthreads();
    if (t == 0) {
        for (int j = 0; j < 8; ++j) {
            float best = -INFINITY; int bi = 0;
            for (int i = 0; i < 256; ++i)
                if (sws[i] > best) { best = sws[i]; bi = i; }
            iw[j] = bi; sws[bi] = -INFINITY;
        }
    }
    __syncthreads();
    for (int e = t; e < 64 * 32; e += 256) {
        int j = e >> 5, y = e & 31;
        int dh = ih[j >> 3], x = iw[j & 7];
        size_t koff = ((size_t)b * 768 + 256 + head * 32 + dh) * S_ + x * 32 + y;
        k2[(bh * 64 + j) * 32 + y] = qkv[koff];
        v2[(bh * 64 + j) * 32 + y] = qkv[koff + (size_t)256 * S_];
    }
}

// ---------------- attention: 8192 rows x 64 keys per bh ----------------
__global__ __launch_bounds__(256) void attn_kernel(const float* __restrict__ qkv,
                                                   const float* __restrict__ k2g,
                                                   const float* __restrict__ v2g,
                                                   float* __restrict__ outimg) {
    int bh = blockIdx.y; int b = bh >> 3, head = bh & 7;
    int i0 = blockIdx.x * 32;
    int t = threadIdx.x, w = t >> 5, lane = t & 31;
    __shared__ float k2s[64 * 33];
    __shared__ float v2s[64 * 33];
    __shared__ float tile[32 * 33];
    for (int e = t; e < 64 * 32; e += 256) {
        int j = e >> 5, y = e & 31;
        k2s[j * 33 + y] = k2g[(bh * 64 + j) * 32 + y];
        v2s[j * 33 + y] = v2g[(bh * 64 + j) * 32 + y];
    }
    __syncthreads();
    const float* qbase = qkv + ((size_t)b * 768 + head * 32) * S_;
    for (int r = w; r < 32; r += 8) {
        int i  = i0 + r;
        int dh = i >> 8, x = i & 255;
        float qv = qbase[(size_t)dh * S_ + x * 32 + lane];
        float s0 = 0.f, s1 = 0.f;
#pragma unroll
        for (int y = 0; y < 32; ++y) {
            float qy = __shfl_sync(0xffffffffu, qv, y);
            s0 = fmaf(qy, k2s[lane * 33 + y], s0);
            s1 = fmaf(qy, k2s[(lane + 32) * 33 + y], s1);
        }
        float m = fmaxf(s0, s1);
#pragma unroll
        for (int o = 16; o > 0; o >>= 1) m = fmaxf(m, __shfl_xor_sync(0xffffffffu, m, o));
        float p0 = expf(s0 - m), p1 = expf(s1 - m);
        float sum = p0 + p1;
#pragma unroll
        for (int o = 16; o > 0; o >>= 1) sum += __shfl_xor_sync(0xffffffffu, sum, o);
        float inv = 1.f / sum;
        p0 *= inv; p1 *= inv;
        float o = 0.f;
#pragma unroll
        for (int j = 0; j < 32; ++j) {
            float pj = __shfl_sync(0xffffffffu, p0, j);
            o = fmaf(pj, v2s[j * 33 + lane], o);
        }
#pragma unroll
        for (int j = 0; j < 32; ++j) {
            float pj = __shfl_sync(0xffffffffu, p1, j);
            o = fmaf(pj, v2s[(j + 32) * 33 + lane], o);
        }
        tile[r * 33 + lane] = o;
    }
    __syncthreads();
    for (int e = t; e < 1024; e += 256) {
        int d = e >> 5, rr = e & 31;
        outimg[((size_t)b * 256 + head * 32 + d) * S_ + i0 + rr] = tile[rr * 33 + d];
    }
}

// ---------------- depthwise 3x3 on x (SAME), simple ----------------
__global__ void dwconv_kernel(const float* __restrict__ in, const float* __restrict__ wgt,
                              const float* __restrict__ bias, float* __restrict__ out, int Cch) {
    int idx = blockIdx.x * blockDim.x + threadIdx.x;
    int s = idx & (S_ - 1);
    int c = (idx >> 13) % Cch;
    int b = idx / (Cch * S_);
    int h = s >> 5, wv = s & 31;
    const float* p  = in + ((size_t)b * Cch + c) * S_;
    const float* wp = wgt + c * 9;
    float acc = bias[c];
#pragma unroll
    for (int dy = -1; dy <= 1; ++dy) {
        int h2 = h + dy;
        if (h2 < 0 || h2 >= H_) continue;
#pragma unroll
        for (int dx = -1; dx <= 1; ++dx) {
            int w2 = wv + dx;
            if (w2 < 0 || w2 >= W_) continue;
            acc = fmaf(wp[(dy + 1) * 3 + (dx + 1)], p[h2 * 32 + w2], acc);
        }
    }
    out[idx] = acc;
}

// ---------------- fused FF middle: h2 = g1 + gelu(inorm(dw3x3(g1))), g1=gelu(inorm(ff1)) ----
__global__ __launch_bounds__(256) void ff_middle_kernel(
    const float* __restrict__ ff1raw, const float* __restrict__ wgt,
    const float* __restrict__ bias, float* __restrict__ h2out)
{
    __shared__ float img[S_];
    __shared__ float red1[256], red2[256];
    const int row = blockIdx.x;                  // b*FFn + c
    const int c   = row & (FFn - 1);
    const int t   = threadIdx.x;
    const float* src = ff1raw + (size_t)row * S_;
    float* dst = h2out + (size_t)row * S_;

    float sum = 0.f, sq = 0.f;
#pragma unroll
    for (int k = 0; k < 8; ++k) {
        float4 v = reinterpret_cast<const float4*>(src)[t + k * 256];
        reinterpret_cast<float4*>(img)[t + k * 256] = v;
        sum += v.x + v.y + v.z + v.w;
        sq  += v.x * v.x + v.y * v.y + v.z * v.z + v.w * v.w;
    }
    red1[t] = sum; red2[t] = sq; __syncthreads();
    for (int o = 128; o > 0; o >>= 1) {
        if (t < o) { red1[t] += red1[t + o]; red2[t] += red2[t + o]; }
        __syncthreads();
    }
    float m1 = red1[0] * (1.f / S_);
    float rs1 = rsqrtf(red2[0] * (1.f / S_) - m1 * m1 + EPSn);

#pragma unroll
    for (int k = 0; k < 8; ++k) {
        float4 v = reinterpret_cast<float4*>(img)[t + k * 256];
        v.x = gelu_f((v.x - m1) * rs1);
        v.y = gelu_f((v.y - m1) * rs1);
        v.z = gelu_f((v.z - m1) * rs1);
        v.w = gelu_f((v.w - m1) * rs1);
        reinterpret_cast<float4*>(img)[t + k * 256] = v;
    }
    __syncthreads();

    float wp[9];
#pragma unroll
    for (int j = 0; j < 9; ++j) wp[j] = wgt[c * 9 + j];
    float bv = bias[c];
    float o[32];
    float sum2 = 0.f, sq2 = 0.f;
#pragma unroll
    for (int k = 0; k < 32; ++k) {
        int idx = t + k * 256;
        int h = idx >> 5, wv = idx & 31;
        float acc = bv;
#pragma unroll
        for (int dy = -1; dy <= 1; ++dy) {
            int h2 = h + dy;
            if (h2 < 0 || h2 >= H_) continue;
#pragma unroll
            for (int dx = -1; dx <= 1; ++dx) {
                int w2 = wv + dx;
                if (w2 < 0 || w2 >= W_) continue;
                acc = fmaf(wp[(dy + 1) * 3 + (dx + 1)], img[h2 * 32 + w2], acc);
            }
        }
        o[k] = acc; sum2 += acc; sq2 += acc * acc;
    }
    __syncthreads();
    red1[t] = sum2; red2[t] = sq2; __syncthreads();
    for (int oo = 128; oo > 0; oo >>= 1) {
        if (t < oo) { red1[t] += red1[t + oo]; red2[t] += red2[t + oo]; }
        __syncthreads();
    }
    float m2 = red1[0] * (1.f / S_);
    float rs2 = rsqrtf(red2[0] * (1.f / S_) - m2 * m2 + EPSn);

#pragma unroll
    for (int k = 0; k < 32; ++k) {
        int idx = t + k * 256;
        dst[idx] = img[idx] + gelu_f((o[k] - m2) * rs2);
    }
}

// ---------------- fused final instance norm: out = inorm(row) ----------------
__global__ __launch_bounds__(256) void final_norm_kernel(
    const float* __restrict__ src, float* __restrict__ dst)
{
    __shared__ float red1[256], red2[256];
    const int row = blockIdx.x;
    const int t = threadIdx.x;
    const float4* s4 = reinterpret_cast<const float4*>(src + (size_t)row * S_);
    float4* d4 = reinterpret_cast<float4*>(dst + (size_t)row * S_);
    float4 loc[8];
    float sum = 0.f, sq = 0.f;
#pragma unroll
    for (int k = 0; k < 8; ++k) {
        float4 v = s4[t + k * 256];
        loc[k] = v;
        sum += v.x + v.y + v.z + v.w;
        sq  += v.x * v.x + v.y * v.y + v.z * v.z + v.w * v.w;
    }
    red1[t] = sum; red2[t] = sq; __syncthreads();
    for (int o = 128; o > 0; o >>= 1) {
        if (t < o) { red1[t] += red1[t + o]; red2[t] += red2[t + o]; }
        __syncthreads();
    }
    float m = red1[0] * (1.f / S_);
    float rs = rsqrtf(red2[0] * (1.f / S_) - m * m + EPSn);
#pragma unroll
    for (int k = 0; k < 8; ++k) {
        float4 v = loc[k];
        v.x = (v.x - m) * rs; v.y = (v.y - m) * rs;
        v.z = (v.z - m) * rs; v.w = (v.w - m) * rs;
        d4[t + k * 256] = v;
    }
}

// ---------------- host orchestration ----------------
extern "C" void kernel_launch(void* const* d_in, const int* in_sizes, int n_in,
                              void* d_out, int out_size) {
    const float* x      = (const float*)d_in[0];
    const float* cg     = (const float*)d_in[1];
    const float* cb     = (const float*)d_in[2];
    const float* w_qkv  = (const float*)d_in[3];
    const float* w_out  = (const float*)d_in[4];
    const float* b_out  = (const float*)d_in[5];
    const float* w_dw   = (const float*)d_in[6];
    const float* b_dw   = (const float*)d_in[7];
    const float* w_comb = (const float*)d_in[8];
    const float* b_comb = (const float*)d_in[9];
    const float* w_ff1  = (const float*)d_in[10];
    const float* b_ff1  = (const float*)d_in[11];
    const float* w_ffdw = (const float*)d_in[12];
    const float* b_ffdw = (const float*)d_in[13];
    const float* w_ff2  = (const float*)d_in[14];
    const float* b_ff2  = (const float*)d_in[15];
    float* out = (float*)d_out;

    float *qkv, *bufa, *bufb, *bufc, *ff1, *ffdw;
    float *cmean, *crstd, *qpart, *ksumH, *k2, *v2;
    void* p;
    cudaGetSymbolAddress(&p, g_qkv);    qkv    = (float*)p;
    cudaGetSymbolAddress(&p, g_bufa);   bufa   = (float*)p;
    cudaGetSymbolAddress(&p, g_bufb);   bufb   = (float*)p;
    cudaGetSymbolAddress(&p, g_bufc);   bufc   = (float*)p;
    cudaGetSymbolAddress(&p, g_ff1);    ff1    = (float*)p;
    cudaGetSymbolAddress(&p, g_ffdw);   ffdw   = (float*)p;
    cudaGetSymbolAddress(&p, g_cmean);  cmean  = (float*)p;
    cudaGetSymbolAddress(&p, g_crstd);  crstd  = (float*)p;
    cudaGetSymbolAddress(&p, g_qpart);  qpart  = (float*)p;
    cudaGetSymbolAddress(&p, g_ksumH);  ksumH  = (float*)p;
    cudaGetSymbolAddress(&p, g_k2);     k2     = (float*)p;
    cudaGetSymbolAddress(&p, g_v2);     v2     = (float*)p;

    // 1) channel layernorm stats
    cln_stats_kernel<<<Bn * S_ / 256, 256>>>(x, cmean, crstd);

    // 2) qkv = conv1x1(CLN(x), w_qkv)
    gemm_f16_kernel<1, false><<<dim3(S_ / 128, 768 / 128, Bn), 256>>>(
        x, nullptr, w_qkv, nullptr, nullptr, cmean, crstd, cg, cb, qkv, 256, 768);

    // 3) L2-normalize q and k rows
    l2norm_kernel<<<(Bn * 512 * H_) / 8, 256>>>(qkv);

    // 4) probe partials + key reductions
    qprobe_kernel<<<BHn * 8, 256>>>(qkv, qpart);
    ksumh_kernel<<<(BHn * 32 * 32) / 256, 256>>>(qkv, ksumH);

    // 5) top-k selection + gather
    select_kernel<<<BHn, 256>>>(qkv, qpart, ksumH, k2, v2);

    // 6) attention -> o image (bufc)
    attn_kernel<<<dim3(S_ / 32, BHn), 256>>>(qkv, k2, v2, bufc);

    // 7) attn branch: conv1x1(o, w_out) + b_out -> bufa
    gemm_f16_kernel<0, false><<<dim3(S_ / 128, 256 / 128, Bn), 256>>>(
        bufc, nullptr, w_out, b_out, nullptr, nullptr, nullptr, nullptr, nullptr, bufa, 256, 256);

    // 8) conv branch: depthwise 3x3 on x -> bufb
    dwconv_kernel<<<(Bn * Cn * S_) / 256, 256>>>(x, w_dw, b_dw, bufb, Cn);

    // 9) combine: conv1x1(concat(bufa,bufb), w_comb) + b_comb + x -> bufc
    gemm_f16_kernel<2, true><<<dim3(S_ / 128, 256 / 128, Bn), 256>>>(
        bufa, bufb, w_comb, b_comb, x, nullptr, nullptr, nullptr, nullptr, bufc, 512, 256);

    // 10) ff1 raw: conv1x1 -> ff1
    gemm_f16_kernel<0, false><<<dim3(S_ / 128, FFn / 128, Bn), 256>>>(
        bufc, nullptr, w_ff1, b_ff1, nullptr, nullptr, nullptr, nullptr, nullptr, ff1, 256, FFn);

    // 11) fused FF middle: ff1(raw) -> h2 (ffdw)
    ff_middle_kernel<<<Bn * FFn, 256>>>(ff1, w_ffdw, b_ffdw, ffdw);

    // 12) ff2: conv1x1(h2) -> bufc;  final instance norm -> out
    gemm_f16_kernel<0, false><<<dim3(S_ / 128, 256 / 128, Bn), 256>>>(
        ffdw, nullptr, w_ff2, b_ff2, nullptr, nullptr, nullptr, nullptr, nullptr, bufc, FFn, 256);
    final_norm_kernel<<<Bn * Cn, 256>>>(bufc, out);
}

// round 8
// speedup vs baseline: 2.5060x; 1.1248x over previous
#include <cuda_runtime.h>
#include <cuda_fp16.h>
#include <math.h>
#include <stdint.h>

// ---------------- problem constants ----------------
constexpr int Bn    = 8;
constexpr int Cn    = 256;
constexpr int H_    = 256;
constexpr int W_    = 32;
constexpr int S_    = H_ * W_;      // 8192
constexpr int HEADS = 8;
constexpr int BHn   = Bn * HEADS;   // 64
constexpr int FFn   = 1024;
constexpr float EPSn = 1e-5f;

// ---------------- scratch (device globals; no runtime alloc) ----------------
__device__ float g_qkv [Bn * 768 * S_];
__device__ float g_bufa[Bn * Cn  * S_];   // half: o image
__device__ float g_bufb[Bn * Cn  * S_];   // half: dwconv branch
__device__ float g_bufc[Bn * Cn  * S_];   // half: comb out | fp32: ff2 out
__device__ float g_ff1 [Bn * FFn * S_];   // half: ff1 raw
__device__ float g_ffdw[Bn * FFn * S_];   // half: h2
__device__ float g_cmean[Bn * S_];
__device__ float g_crstd[Bn * S_];
__device__ float g_qpart[BHn * 8 * 32];
__device__ float g_ksumH [BHn * 32 * 32];
__device__ float g_k2[BHn * 64 * 32];
__device__ float g_v2[BHn * 64 * 32];
__device__ float g_wm[256 * 256];         // merged w_comb1 @ w_out
__device__ float g_bm[256];               // merged bias

// ---------------- helpers ----------------
__device__ __forceinline__ uint32_t smem_u32(const void* p) {
    return (uint32_t)__cvta_generic_to_shared(p);
}

__device__ __forceinline__ void ldsm_x4(uint32_t* r, uint32_t a) {
    asm volatile("ldmatrix.sync.aligned.m8n8.x4.shared.b16 {%0,%1,%2,%3}, [%4];"
        : "=r"(r[0]), "=r"(r[1]), "=r"(r[2]), "=r"(r[3]) : "r"(a));
}

__device__ __forceinline__ void ldsm_x4t(uint32_t* r, uint32_t a) {
    asm volatile("ldmatrix.sync.aligned.m8n8.x4.trans.shared.b16 {%0,%1,%2,%3}, [%4];"
        : "=r"(r[0]), "=r"(r[1]), "=r"(r[2]), "=r"(r[3]) : "r"(a));
}

__device__ __forceinline__ void mma_f16(float* d, const uint32_t* a, const uint32_t* b) {
    asm volatile(
        "mma.sync.aligned.m16n8k16.row.col.f32.f16.f16.f32 "
        "{%0,%1,%2,%3}, {%4,%5,%6,%7}, {%8,%9}, {%0,%1,%2,%3};"
        : "+f"(d[0]), "+f"(d[1]), "+f"(d[2]), "+f"(d[3])
        : "r"(a[0]), "r"(a[1]), "r"(a[2]), "r"(a[3]), "r"(b[0]), "r"(b[1]));
}

__device__ __forceinline__ float gelu_f(float x) {
    return 0.5f * x * (1.f + erff(x * 0.7071067811865475f));
}

// ---------------- weight merge: Wm = w_comb[:, :256] @ w_out ----------------
__global__ void wmerge_kernel(const float* __restrict__ w_comb,
                              const float* __restrict__ w_out,
                              float* __restrict__ wm) {
    int n = blockIdx.x, k = threadIdx.x;
    const float* wc = w_comb + (size_t)n * 512;
    float s = 0.f;
#pragma unroll 4
    for (int j = 0; j < 256; ++j) s = fmaf(wc[j], w_out[j * 256 + k], s);
    wm[n * 256 + k] = s;
}

__global__ void bmerge_kernel(const float* __restrict__ w_comb,
                              const float* __restrict__ b_out,
                              const float* __restrict__ b_comb,
                              float* __restrict__ bm) {
    int n = threadIdx.x;
    const float* wc = w_comb + (size_t)n * 512;
    float s = b_comb[n];
#pragma unroll 4
    for (int j = 0; j < 256; ++j) s = fmaf(wc[j], b_out[j], s);
    bm[n] = s;
}

// ---------------- channel layernorm stats (over C for each (b,s)) ----------------
__global__ void cln_stats_kernel(const float* __restrict__ x,
                                 float* __restrict__ mean, float* __restrict__ rstd) {
    int b = blockIdx.x / (S_ / 256);
    int s = (blockIdx.x % (S_ / 256)) * 256 + threadIdx.x;
    const float* p = x + (size_t)b * Cn * S_ + s;
    float sum = 0.f, sq = 0.f;
#pragma unroll 4
    for (int c = 0; c < Cn; ++c) {
        float v = p[(size_t)c * S_];
        sum += v; sq += v * v;
    }
    float m = sum * (1.f / Cn);
    float var = sq * (1.f / Cn) - m * m;
    mean[b * S_ + s] = m;
    rstd[b * S_ + s] = rsqrtf(var + EPSn);
}

// ---------------- fp16 tensor-core GEMM (double-buffered, ldmatrix) ----------------
// Out[b,n,s] = sum_k W[n,k]*A[b,k,s]
// MODE 0: plain A0;  MODE 1: channel-LN of fp32 A0 on load;  MODE 2: concat(A0,A1), W split
// AH: A buffers are __half;  OH: output stored as __half
constexpr int WS_STR = 24;    // halves per n-row (16 + 8 pad)
constexpr int AS_STR = 136;   // halves per k-row (128 + 8 pad)

template<int MODE, bool RES, bool AH, bool OH>
__global__ __launch_bounds__(256) void gemm_f16_kernel(
    const void* __restrict__ A0v, const void* __restrict__ A1v,
    const float* __restrict__ W0, const float* __restrict__ W1,
    int sw0, int sw1,
    const float* __restrict__ bias, const float* __restrict__ resid,
    const float* __restrict__ cmean, const float* __restrict__ crstd,
    const float* __restrict__ gamma, const float* __restrict__ beta,
    void* __restrict__ Outv, int K, int N)
{
    __shared__ __align__(16) __half Ws[2][128 * WS_STR];  // [n][k]
    __shared__ __align__(16) __half As[2][16 * AS_STR];   // [k][s]
    const int b  = blockIdx.z;
    const int s0 = blockIdx.x * 128;
    const int n0 = blockIdx.y * 128;
    const int t  = threadIdx.x;
    const int lane = t & 31, warp = t >> 5;
    const int wn = warp & 3, ws = warp >> 2;
    const int n0w = wn * 32, s0w = ws * 64;
    const int r = lane >> 2, c = lane & 3;

    float acc[2][8][4];
#pragma unroll
    for (int mt = 0; mt < 2; ++mt)
#pragma unroll
        for (int nt = 0; nt < 8; ++nt)
#pragma unroll
            for (int q = 0; q < 4; ++q) acc[mt][nt][q] = 0.f;

    const int wkq = (t & 3) * 4;
    const int wnl = t >> 2;
    const int asl = (t & 31) * 4;
    const int akl = t >> 5;

    uint32_t aA[2][2], aB[2][4];
#pragma unroll
    for (int bi = 0; bi < 2; ++bi) {
#pragma unroll
        for (int mt = 0; mt < 2; ++mt) {
            int row = n0w + mt * 16 + (lane & 7) + ((lane >> 3) & 1) * 8;
            int kofs = (lane >> 4) * 8;
            aA[bi][mt] = smem_u32(&Ws[bi][row * WS_STR + kofs]);
        }
#pragma unroll
        for (int ntp = 0; ntp < 4; ++ntp) {
            int k = (lane & 7) + ((lane >> 3) & 1) * 8;
            int col = s0w + (ntp * 2 + (lane >> 4)) * 8;
            aB[bi][ntp] = smem_u32(&As[bi][k * AS_STR + col]);
        }
    }

    float4 m4, r4;
    if (MODE == 1) {
        m4 = *reinterpret_cast<const float4*>(cmean + (size_t)b * S_ + s0 + asl);
        r4 = *reinterpret_cast<const float4*>(crstd + (size_t)b * S_ + s0 + asl);
    }

    float4 wreg[2];
    float4 areg_f[2];
    uint2  areg_h[2];
    float  gA[2], bA[2];

    auto load_tile = [&](int k0) {
#pragma unroll
        for (int pass = 0; pass < 2; ++pass) {
            int n = n0 + wnl + pass * 64;
            int kg = k0 + wkq;
            const float* wsrc;
            if (MODE == 2)
                wsrc = (kg < 256) ? (W0 + (size_t)n * sw0 + kg)
                                  : (W1 + (size_t)n * sw1 + kg);
            else
                wsrc = W0 + (size_t)n * sw0 + kg;
            wreg[pass] = *reinterpret_cast<const float4*>(wsrc);
        }
#pragma unroll
        for (int pass = 0; pass < 2; ++pass) {
            int k  = akl + pass * 8;
            int kg = k0 + k;
            if (AH) {
                const __half* src;
                if (MODE == 2) {
                    src = (kg < 256)
                        ? ((const __half*)A0v + ((size_t)b * 256 + kg) * S_)
                        : ((const __half*)A1v + ((size_t)b * 256 + (kg - 256)) * S_);
                } else {
                    src = (const __half*)A0v + ((size_t)b * K + kg) * S_;
                }
                areg_h[pass] = *reinterpret_cast<const uint2*>(src + s0 + asl);
            } else {
                const float* src = (const float*)A0v + ((size_t)b * K + kg) * S_;
                areg_f[pass] = *reinterpret_cast<const float4*>(src + s0 + asl);
                if (MODE == 1) { gA[pass] = gamma[kg]; bA[pass] = beta[kg]; }
            }
        }
    };

    auto sts_tile = [&](int bi) {
#pragma unroll
        for (int pass = 0; pass < 2; ++pass) {
            int n = wnl + pass * 64;
            float4 w4 = wreg[pass];
            __half2* dst = reinterpret_cast<__half2*>(&Ws[bi][n * WS_STR + wkq]);
            dst[0] = __floats2half2_rn(w4.x, w4.y);
            dst[1] = __floats2half2_rn(w4.z, w4.w);
        }
#pragma unroll
        for (int pass = 0; pass < 2; ++pass) {
            int k = akl + pass * 8;
            if (AH) {
                *reinterpret_cast<uint2*>(&As[bi][k * AS_STR + asl]) = areg_h[pass];
            } else {
                float4 a4 = areg_f[pass];
                if (MODE == 1) {
                    float g = gA[pass], be = bA[pass];
                    a4.x = (a4.x - m4.x) * r4.x * g + be;
                    a4.y = (a4.y - m4.y) * r4.y * g + be;
                    a4.z = (a4.z - m4.z) * r4.z * g + be;
                    a4.w = (a4.w - m4.w) * r4.w * g + be;
                }
                __half2* dst = reinterpret_cast<__half2*>(&As[bi][k * AS_STR + asl]);
                dst[0] = __floats2half2_rn(a4.x, a4.y);
                dst[1] = __floats2half2_rn(a4.z, a4.w);
            }
        }
    };

    auto compute = [&](int bi) {
        uint32_t af[2][4];
        ldsm_x4(af[0], aA[bi][0]);
        ldsm_x4(af[1], aA[bi][1]);
        uint32_t bf[8][2];
#pragma unroll
        for (int ntp = 0; ntp < 4; ++ntp) {
            uint32_t rr[4];
            ldsm_x4t(rr, aB[bi][ntp]);
            bf[2 * ntp][0] = rr[0]; bf[2 * ntp][1] = rr[1];
            bf[2 * ntp + 1][0] = rr[2]; bf[2 * ntp + 1][1] = rr[3];
        }
#pragma unroll
        for (int mt = 0; mt < 2; ++mt)
#pragma unroll
            for (int nt = 0; nt < 8; ++nt)
                mma_f16(acc[mt][nt], af[mt], bf[nt]);
    };

    const int nt_iters = K / 16;
    load_tile(0);
    sts_tile(0);
    __syncthreads();
    for (int it = 1; it < nt_iters; ++it) {
        load_tile(it * 16);
        compute((it - 1) & 1);
        sts_tile(it & 1);
        __syncthreads();
    }
    compute((nt_iters - 1) & 1);

    // epilogue
#pragma unroll
    for (int mt = 0; mt < 2; ++mt) {
#pragma unroll
        for (int half = 0; half < 2; ++half) {
            int n = n0 + n0w + mt * 16 + r + half * 8;
            float bv = (bias != nullptr) ? bias[n] : 0.f;
            const float* rrow = RES ? (resid + ((size_t)n + (size_t)b * N) * S_) : nullptr;
#pragma unroll
            for (int nt = 0; nt < 8; ++nt) {
                int s = s0 + s0w + nt * 8 + 2 * c;
                float ox = acc[mt][nt][half * 2 + 0] + bv;
                float oy = acc[mt][nt][half * 2 + 1] + bv;
                if (RES) {
                    float2 rv = *reinterpret_cast<const float2*>(rrow + s);
                    ox += rv.x; oy += rv.y;
                }
                if (OH) {
                    __half* orow = (__half*)Outv + ((size_t)b * N + n) * S_;
                    *reinterpret_cast<__half2*>(orow + s) = __floats2half2_rn(ox, oy);
                } else {
                    float* orow = (float*)Outv + ((size_t)b * N + n) * S_;
                    float2 o; o.x = ox; o.y = oy;
                    *reinterpret_cast<float2*>(orow + s) = o;
                }
            }
        }
    }
}

// ---------------- L2 normalize q and k rows over W (32 contiguous) ----------------
__global__ void l2norm_kernel(float* __restrict__ qkv) {
    int gw   = (blockIdx.x * blockDim.x + threadIdx.x) >> 5;
    int lane = threadIdx.x & 31;
    int x  = gw % H_;
    int ch = (gw / H_) % 512;
    int b  = gw / (H_ * 512);
    float* p = qkv + ((size_t)b * 768 + ch) * S_ + x * W_ + lane;
    float v = *p;
    float sq = v * v;
#pragma unroll
    for (int o = 16; o > 0; o >>= 1) sq += __shfl_xor_sync(0xffffffffu, sq, o);
    float nrm = fmaxf(sqrtf(sq), 1e-12f);
    *p = v / nrm;
}

// ---------------- q_probe partials ----------------
__global__ void qprobe_kernel(const float* __restrict__ qkv, float* __restrict__ qpart) {
    int bp = blockIdx.x;
    int bh = bp >> 3, part = bp & 7;
    int b = bh >> 3, head = bh & 7;
    int t = threadIdx.x, y = t & 31, sub = t >> 5;
    const float* base = qkv + ((size_t)b * 768 + head * 32) * S_;
    float acc = 0.f;
    for (int rr = sub * 128; rr < sub * 128 + 128; ++rr) {
        int dh = rr >> 5;
        int x  = part * 32 + (rr & 31);
        acc += base[(size_t)dh * S_ + x * 32 + y];
    }
    __shared__ float sh[256];
    sh[t] = acc;
    __syncthreads();
    if (t < 32) {
        float s = 0.f;
#pragma unroll
        for (int p = 0; p < 8; ++p) s += sh[p * 32 + t];
        qpart[bp * 32 + t] = s;
    }
}

// ---------------- ksumH[bh,dh,y] = sum_x kn ----------------
__global__ void ksumh_kernel(const float* __restrict__ qkv, float* __restrict__ ksumH) {
    int idx = blockIdx.x * blockDim.x + threadIdx.x;
    int y = idx & 31, dh = (idx >> 5) & 31, bh = idx >> 10;
    int b = bh >> 3, head = bh & 7;
    const float* p = qkv + ((size_t)b * 768 + 256 + head * 32 + dh) * S_ + y;
    float s = 0.f;
    for (int x = 0; x < H_; ++x) s += p[x * 32];
    ksumH[idx] = s;
}

// ---------------- top-k selection + gather ----------------
__global__ void select_kernel(const float* __restrict__ qkv,
                              const float* __restrict__ qpart,
                              const float* __restrict__ ksumH,
                              float* __restrict__ k2, float* __restrict__ v2) {
    int bh = blockIdx.x; int b = bh >> 3, head = bh & 7;
    int t = threadIdx.x;
    __shared__ float qp[32];
    __shared__ float shs[32];
    __shared__ int   ih[8];
    __shared__ float sws[256];
    __shared__ int   iw[8];

    if (t < 32) {
        float s = 0.f;
#pragma unroll
        for (int p = 0; p < 8; ++p) s += qpart[(bh * 8 + p) * 32 + t];
        qp[t] = s;
    }
    __syncthreads();
    if (t < 32) {
        float s = 0.f;
        const float* kr = ksumH + (bh * 32 + t) * 32;
#pragma unroll
        for (int y = 0; y < 32; ++y) s += qp[y] * kr[y];
        shs[t] = s;
    }
    __syncthreads();
    if (t == 0) {
        for (int j = 0; j < 8; ++j) {
            float best = -INFINITY; int bi = 0;
            for (int i = 0; i < 32; ++i)
                if (shs[i] > best) { best = shs[i]; bi = i; }
            ih[j] = bi; shs[bi] = -INFINITY;
        }
    }
    __syncthreads();
    {
        int x = t;
        float s = 0.f;
        const float* kbase = qkv + ((size_t)b * 768 + 256 + head * 32) * S_ + x * 32;
        for (int j = 0; j < 8; ++j) {
            const float* kp = kbase + (size_t)ih[j] * S_;
#pragma unroll
            for (int y = 0; y < 32; ++y) s += kp[y] * qp[y];
        }
        sws[x] = s;
    }
    __syncthreads();
    if (t == 0) {
        for (int j = 0; j < 8; ++j) {
            float best = -INFINITY; int bi = 0;
            for (int i = 0; i < 256; ++i)
                if (sws[i] > best) { best = sws[i]; bi = i; }
            iw[j] = bi; sws[bi] = -INFINITY;
        }
    }
    __syncthreads();
    for (int e = t; e < 64 * 32; e += 256) {
        int j = e >> 5, y = e & 31;
        int dh = ih[j >> 3], x = iw[j & 7];
        size_t koff = ((size_t)b * 768 + 256 + head * 32 + dh) * S_ + x * 32 + y;
        k2[(bh * 64 + j) * 32 + y] = qkv[koff];
        v2[(bh * 64 + j) * 32 + y] = qkv[koff + (size_t)256 * S_];
    }
}

// ---------------- attention: 8192 rows x 64 keys per bh; half output ----------------
__global__ __launch_bounds__(256) void attn_kernel(const float* __restrict__ qkv,
                                                   const float* __restrict__ k2g,
                                                   const float* __restrict__ v2g,
                                                   __half* __restrict__ outimg) {
    int bh = blockIdx.y; int b = bh >> 3, head = bh & 7;
    int i0 = blockIdx.x * 32;
    int t = threadIdx.x, w = t >> 5, lane = t & 31;
    __shared__ float k2s[64 * 33];
    __shared__ float v2s[64 * 33];
    __shared__ float tile[32 * 33];
    for (int e = t; e < 64 * 32; e += 256) {
        int j = e >> 5, y = e & 31;
        k2s[j * 33 + y] = k2g[(bh * 64 + j) * 32 + y];
        v2s[j * 33 + y] = v2g[(bh * 64 + j) * 32 + y];
    }
    __syncthreads();
    const float* qbase = qkv + ((size_t)b * 768 + head * 32) * S_;
    for (int r = w; r < 32; r += 8) {
        int i  = i0 + r;
        int dh = i >> 8, x = i & 255;
        float qv = qbase[(size_t)dh * S_ + x * 32 + lane];
        float s0 = 0.f, s1 = 0.f;
#pragma unroll
        for (int y = 0; y < 32; ++y) {
            float qy = __shfl_sync(0xffffffffu, qv, y);
            s0 = fmaf(qy, k2s[lane * 33 + y], s0);
            s1 = fmaf(qy, k2s[(lane + 32) * 33 + y], s1);
        }
        float m = fmaxf(s0, s1);
#pragma unroll
        for (int o = 16; o > 0; o >>= 1) m = fmaxf(m, __shfl_xor_sync(0xffffffffu, m, o));
        float p0 = expf(s0 - m), p1 = expf(s1 - m);
        float sum = p0 + p1;
#pragma unroll
        for (int o = 16; o > 0; o >>= 1) sum += __shfl_xor_sync(0xffffffffu, sum, o);
        float inv = 1.f / sum;
        p0 *= inv; p1 *= inv;
        float o = 0.f;
#pragma unroll
        for (int j = 0; j < 32; ++j) {
            float pj = __shfl_sync(0xffffffffu, p0, j);
            o = fmaf(pj, v2s[j * 33 + lane], o);
        }
#pragma unroll
        for (int j = 0; j < 32; ++j) {
            float pj = __shfl_sync(0xffffffffu, p1, j);
            o = fmaf(pj, v2s[(j + 32) * 33 + lane], o);
        }
        tile[r * 33 + lane] = o;
    }
    __syncthreads();
    for (int e = t; e < 1024; e += 256) {
        int d = e >> 5, rr = e & 31;
        outimg[((size_t)b * 256 + head * 32 + d) * S_ + i0 + rr] = __float2half(tile[rr * 33 + d]);
    }
}

// ---------------- depthwise 3x3 on x (SAME); half output ----------------
__global__ void dwconv_kernel(const float* __restrict__ in, const float* __restrict__ wgt,
                              const float* __restrict__ bias, __half* __restrict__ out, int Cch) {
    int idx = blockIdx.x * blockDim.x + threadIdx.x;
    int s = idx & (S_ - 1);
    int c = (idx >> 13) % Cch;
    int b = idx / (Cch * S_);
    int h = s >> 5, wv = s & 31;
    const float* p  = in + ((size_t)b * Cch + c) * S_;
    const float* wp = wgt + c * 9;
    float acc = bias[c];
#pragma unroll
    for (int dy = -1; dy <= 1; ++dy) {
        int h2 = h + dy;
        if (h2 < 0 || h2 >= H_) continue;
#pragma unroll
        for (int dx = -1; dx <= 1; ++dx) {
            int w2 = wv + dx;
            if (w2 < 0 || w2 >= W_) continue;
            acc = fmaf(wp[(dy + 1) * 3 + (dx + 1)], p[h2 * 32 + w2], acc);
        }
    }
    out[idx] = __float2half(acc);
}

// ---------------- fused FF middle (half in/out): h2 = g1 + gelu(inorm(dw3x3(g1))) ----
__global__ __launch_bounds__(256) void ff_middle_kernel(
    const __half* __restrict__ ff1raw, const float* __restrict__ wgt,
    const float* __restrict__ bias, __half* __restrict__ h2out)
{
    __shared__ float img[S_];
    __shared__ float red1[256], red2[256];
    const int row = blockIdx.x;                  // b*FFn + c
    const int c   = row & (FFn - 1);
    const int t   = threadIdx.x;
    const __half* src = ff1raw + (size_t)row * S_;
    __half* dst = h2out + (size_t)row * S_;

    // stage 1: load (half->float) + stats
    float sum = 0.f, sq = 0.f;
#pragma unroll
    for (int k = 0; k < 4; ++k) {
        uint4 raw = reinterpret_cast<const uint4*>(src)[t + k * 256];
        const __half2* h2p = reinterpret_cast<const __half2*>(&raw);
        int base = (t + k * 256) * 8;
#pragma unroll
        for (int q = 0; q < 4; ++q) {
            float2 f = __half22float2(h2p[q]);
            img[base + 2 * q] = f.x;
            img[base + 2 * q + 1] = f.y;
            sum += f.x + f.y;
            sq  += f.x * f.x + f.y * f.y;
        }
    }
    red1[t] = sum; red2[t] = sq; __syncthreads();
    for (int o = 128; o > 0; o >>= 1) {
        if (t < o) { red1[t] += red1[t + o]; red2[t] += red2[t + o]; }
        __syncthreads();
    }
    float m1 = red1[0] * (1.f / S_);
    float rs1 = rsqrtf(red2[0] * (1.f / S_) - m1 * m1 + EPSn);

    // stage 2: g1 = gelu(norm)
#pragma unroll
    for (int k = 0; k < 8; ++k) {
        float4 v = reinterpret_cast<float4*>(img)[t + k * 256];
        v.x = gelu_f((v.x - m1) * rs1);
        v.y = gelu_f((v.y - m1) * rs1);
        v.z = gelu_f((v.z - m1) * rs1);
        v.w = gelu_f((v.w - m1) * rs1);
        reinterpret_cast<float4*>(img)[t + k * 256] = v;
    }
    __syncthreads();

    // stage 3: depthwise 3x3 from smem + stats
    float wp[9];
#pragma unroll
    for (int j = 0; j < 9; ++j) wp[j] = wgt[c * 9 + j];
    float bv = bias[c];
    float o[32];
    float sum2 = 0.f, sq2 = 0.f;
#pragma unroll
    for (int k = 0; k < 32; ++k) {
        int idx = t + k * 256;
        int h = idx >> 5, wv = idx & 31;
        float acc = bv;
#pragma unroll
        for (int dy = -1; dy <= 1; ++dy) {
            int h2 = h + dy;
            if (h2 < 0 || h2 >= H_) continue;
#pragma unroll
            for (int dx = -1; dx <= 1; ++dx) {
                int w2 = wv + dx;
                if (w2 < 0 || w2 >= W_) continue;
                acc = fmaf(wp[(dy + 1) * 3 + (dx + 1)], img[h2 * 32 + w2], acc);
            }
        }
        o[k] = acc; sum2 += acc; sq2 += acc * acc;
    }
    __syncthreads();
    red1[t] = sum2; red2[t] = sq2; __syncthreads();
    for (int oo = 128; oo > 0; oo >>= 1) {
        if (t < oo) { red1[t] += red1[t + oo]; red2[t] += red2[t + oo]; }
        __syncthreads();
    }
    float m2 = red1[0] * (1.f / S_);
    float rs2 = rsqrtf(red2[0] * (1.f / S_) - m2 * m2 + EPSn);

    // stage 4: h2 = g1 + gelu(norm(o))  (half store)
#pragma unroll
    for (int k = 0; k < 32; ++k) {
        int idx = t + k * 256;
        dst[idx] = __float2half(img[idx] + gelu_f((o[k] - m2) * rs2));
    }
}

// ---------------- fused final instance norm: out = inorm(row) ----------------
__global__ __launch_bounds__(256) void final_norm_kernel(
    const float* __restrict__ src, float* __restrict__ dst)
{
    __shared__ float red1[256], red2[256];
    const int row = blockIdx.x;
    const int t = threadIdx.x;
    const float4* s4 = reinterpret_cast<const float4*>(src + (size_t)row * S_);
    float4* d4 = reinterpret_cast<float4*>(dst + (size_t)row * S_);
    float4 loc[8];
    float sum = 0.f, sq = 0.f;
#pragma unroll
    for (int k = 0; k < 8; ++k) {
        float4 v = s4[t + k * 256];
        loc[k] = v;
        sum += v.x + v.y + v.z + v.w;
        sq  += v.x * v.x + v.y * v.y + v.z * v.z + v.w * v.w;
    }
    red1[t] = sum; red2[t] = sq; __syncthreads();
    for (int o = 128; o > 0; o >>= 1) {
        if (t < o) { red1[t] += red1[t + o]; red2[t] += red2[t + o]; }
        __syncthreads();
    }
    float m = red1[0] * (1.f / S_);
    float rs = rsqrtf(red2[0] * (1.f / S_) - m * m + EPSn);
#pragma unroll
    for (int k = 0; k < 8; ++k) {
        float4 v = loc[k];
        v.x = (v.x - m) * rs; v.y = (v.y - m) * rs;
        v.z = (v.z - m) * rs; v.w = (v.w - m) * rs;
        d4[t + k * 256] = v;
    }
}

// ---------------- host orchestration ----------------
extern "C" void kernel_launch(void* const* d_in, const int* in_sizes, int n_in,
                              void* d_out, int out_size) {
    const float* x      = (const float*)d_in[0];
    const float* cg     = (const float*)d_in[1];
    const float* cb     = (const float*)d_in[2];
    const float* w_qkv  = (const float*)d_in[3];
    const float* w_out  = (const float*)d_in[4];
    const float* b_out  = (const float*)d_in[5];
    const float* w_dw   = (const float*)d_in[6];
    const float* b_dw   = (const float*)d_in[7];
    const float* w_comb = (const float*)d_in[8];
    const float* b_comb = (const float*)d_in[9];
    const float* w_ff1  = (const float*)d_in[10];
    const float* b_ff1  = (const float*)d_in[11];
    const float* w_ffdw = (const float*)d_in[12];
    const float* b_ffdw = (const float*)d_in[13];
    const float* w_ff2  = (const float*)d_in[14];
    const float* b_ff2  = (const float*)d_in[15];
    float* out = (float*)d_out;

    float *qkv, *bufa, *bufb, *bufc, *ff1, *ffdw;
    float *cmean, *crstd, *qpart, *ksumH, *k2, *v2, *wm, *bm;
    void* p;
    cudaGetSymbolAddress(&p, g_qkv);    qkv    = (float*)p;
    cudaGetSymbolAddress(&p, g_bufa);   bufa   = (float*)p;
    cudaGetSymbolAddress(&p, g_bufb);   bufb   = (float*)p;
    cudaGetSymbolAddress(&p, g_bufc);   bufc   = (float*)p;
    cudaGetSymbolAddress(&p, g_ff1);    ff1    = (float*)p;
    cudaGetSymbolAddress(&p, g_ffdw);   ffdw   = (float*)p;
    cudaGetSymbolAddress(&p, g_cmean);  cmean  = (float*)p;
    cudaGetSymbolAddress(&p, g_crstd);  crstd  = (float*)p;
    cudaGetSymbolAddress(&p, g_qpart);  qpart  = (float*)p;
    cudaGetSymbolAddress(&p, g_ksumH);  ksumH  = (float*)p;
    cudaGetSymbolAddress(&p, g_k2);     k2     = (float*)p;
    cudaGetSymbolAddress(&p, g_v2);     v2     = (float*)p;
    cudaGetSymbolAddress(&p, g_wm);     wm     = (float*)p;
    cudaGetSymbolAddress(&p, g_bm);     bm     = (float*)p;

    __half* o_h    = reinterpret_cast<__half*>(bufa);
    __half* dw_h   = reinterpret_cast<__half*>(bufb);
    __half* comb_h = reinterpret_cast<__half*>(bufc);
    __half* ff1_h  = reinterpret_cast<__half*>(ff1);
    __half* h2_h   = reinterpret_cast<__half*>(ffdw);

    // 0) merged comb weights (w_comb1 @ w_out, bias)
    wmerge_kernel<<<256, 256>>>(w_comb, w_out, wm);
    bmerge_kernel<<<1, 256>>>(w_comb, b_out, b_comb, bm);

    // 1) channel layernorm stats
    cln_stats_kernel<<<Bn * S_ / 256, 256>>>(x, cmean, crstd);

    // 2) qkv = conv1x1(CLN(x), w_qkv)    (fp32 A, fp32 out)
    gemm_f16_kernel<1, false, false, false><<<dim3(S_ / 128, 768 / 128, Bn), 256>>>(
        x, nullptr, w_qkv, nullptr, 256, 0, nullptr, nullptr,
        cmean, crstd, cg, cb, qkv, 256, 768);

    // 3) L2-normalize q and k rows
    l2norm_kernel<<<(Bn * 512 * H_) / 8, 256>>>(qkv);

    // 4) probe partials + key reductions
    qprobe_kernel<<<BHn * 8, 256>>>(qkv, qpart);
    ksumh_kernel<<<(BHn * 32 * 32) / 256, 256>>>(qkv, ksumH);

    // 5) top-k selection + gather
    select_kernel<<<BHn, 256>>>(qkv, qpart, ksumH, k2, v2);

    // 6) attention -> o image (half)
    attn_kernel<<<dim3(S_ / 32, BHn), 256>>>(qkv, k2, v2, o_h);

    // 7) conv branch: depthwise 3x3 on x -> half
    dwconv_kernel<<<(Bn * Cn * S_) / 256, 256>>>(x, w_dw, b_dw, dw_h, Cn);

    // 8) combined: (wm)@o + w_comb2@dw + bm + x -> half
    gemm_f16_kernel<2, true, true, true><<<dim3(S_ / 128, 256 / 128, Bn), 256>>>(
        o_h, dw_h, wm, w_comb, 256, 512, bm, x,
        nullptr, nullptr, nullptr, nullptr, comb_h, 512, 256);

    // 9) ff1 raw: conv1x1 -> half
    gemm_f16_kernel<0, false, true, true><<<dim3(S_ / 128, FFn / 128, Bn), 256>>>(
        comb_h, nullptr, w_ff1, nullptr, 256, 0, b_ff1, nullptr,
        nullptr, nullptr, nullptr, nullptr, ff1_h, 256, FFn);

    // 10) fused FF middle: ff1(half) -> h2(half)
    ff_middle_kernel<<<Bn * FFn, 256>>>(ff1_h, w_ffdw, b_ffdw, h2_h);

    // 11) ff2: conv1x1(h2) -> fp32; final instance norm -> out
    gemm_f16_kernel<0, false, true, false><<<dim3(S_ / 128, 256 / 128, Bn), 256>>>(
        h2_h, nullptr, w_ff2, nullptr, 1024, 0, b_ff2, nullptr,
        nullptr, nullptr, nullptr, nullptr, bufc, 1024, 256);
    final_norm_kernel<<<Bn * Cn, 256>>>(bufc, out);
}

// round 10
// speedup vs baseline: 2.6968x; 1.0761x over previous
#include <cuda_runtime.h>
#include <cuda_fp16.h>
#include <math.h>
#include <stdint.h>

// ---------------- problem constants ----------------
constexpr int Bn    = 8;
constexpr int Cn    = 256;
constexpr int H_    = 256;
constexpr int W_    = 32;
constexpr int S_    = H_ * W_;      // 8192
constexpr int HEADS = 8;
constexpr int BHn   = Bn * HEADS;   // 64
constexpr int FFn   = 1024;
constexpr float EPSn = 1e-5f;

// ---------------- scratch (device globals; no runtime alloc) ----------------
__device__ float g_qkv [Bn * 768 * S_];   // fp32 qkv
__device__ float g_bufa[Bn * Cn  * S_];   // half [b][512][S]: o image | dw branch
__device__ float g_bufb[Bn * Cn  * S_];   // fp32 ff2 raw out
__device__ float g_bufc[Bn * Cn  * S_];   // half: xn, later comb out
__device__ float g_ff1 [Bn * FFn * S_];   // half: ff1 raw
__device__ float g_ffdw[Bn * FFn * S_];   // half: h2
__device__ float g_qpart[BHn * 8 * 32];
__device__ float g_ksumH [BHn * 32 * 32];
__device__ float g_k2[BHn * 64 * 32];
__device__ float g_v2[BHn * 64 * 32];
__device__ float g_bm[256];
__device__ __half g_whqkv[768 * 256];
__device__ __half g_whcomb[256 * 512];
__device__ __half g_whff1[1024 * 256];
__device__ __half g_whff2[256 * 1024];

// ---------------- helpers ----------------
__device__ __forceinline__ uint32_t smem_u32(const void* p) {
    return (uint32_t)__cvta_generic_to_shared(p);
}
__device__ __forceinline__ void cp16(uint32_t dst, const void* src) {
    asm volatile("cp.async.ca.shared.global [%0], [%1], 16;" :: "r"(dst), "l"(src));
}
__device__ __forceinline__ void cp_commit() { asm volatile("cp.async.commit_group;"); }
template<int N2> __device__ __forceinline__ void cp_wait() {
    asm volatile("cp.async.wait_group %0;" :: "n"(N2));
}
__device__ __forceinline__ void ldsm_x4(uint32_t* r, uint32_t a) {
    asm volatile("ldmatrix.sync.aligned.m8n8.x4.shared.b16 {%0,%1,%2,%3}, [%4];"
        : "=r"(r[0]), "=r"(r[1]), "=r"(r[2]), "=r"(r[3]) : "r"(a));
}
__device__ __forceinline__ void ldsm_x4t(uint32_t* r, uint32_t a) {
    asm volatile("ldmatrix.sync.aligned.m8n8.x4.trans.shared.b16 {%0,%1,%2,%3}, [%4];"
        : "=r"(r[0]), "=r"(r[1]), "=r"(r[2]), "=r"(r[3]) : "r"(a));
}
__device__ __forceinline__ void mma_f16(float* d, const uint32_t* a, const uint32_t* b) {
    asm volatile(
        "mma.sync.aligned.m16n8k16.row.col.f32.f16.f16.f32 "
        "{%0,%1,%2,%3}, {%4,%5,%6,%7}, {%8,%9}, {%0,%1,%2,%3};"
        : "+f"(d[0]), "+f"(d[1]), "+f"(d[2]), "+f"(d[3])
        : "r"(a[0]), "r"(a[1]), "r"(a[2]), "r"(a[3]), "r"(b[0]), "r"(b[1]));
}
__device__ __forceinline__ float gelu_f(float x) {
    return 0.5f * x * (1.f + erff(x * 0.7071067811865475f));
}

// ---------------- weight prep ----------------
__global__ void convert_w_kernel(const float* __restrict__ w, __half* __restrict__ o, int n) {
    int i = blockIdx.x * 256 + threadIdx.x;
    if (i < n) o[i] = __float2half(w[i]);
}

// whcomb[n][0:256] = half(w_comb[n,0:256] @ w_out); whcomb[n][256:512] = half(w_comb[n,256:512])
__global__ void wcombh_kernel(const float* __restrict__ w_comb,
                              const float* __restrict__ w_out,
                              __half* __restrict__ whcomb) {
    int n = blockIdx.x, k = threadIdx.x;
    const float* wc = w_comb + (size_t)n * 512;
    float s = 0.f;
#pragma unroll 4
    for (int j = 0; j < 256; ++j) s = fmaf(wc[j], w_out[j * 256 + k], s);
    whcomb[n * 512 + k] = __float2half(s);
    whcomb[n * 512 + 256 + k] = __float2half(wc[256 + k]);
}

__global__ void bmerge_kernel(const float* __restrict__ w_comb,
                              const float* __restrict__ b_out,
                              const float* __restrict__ b_comb,
                              float* __restrict__ bm) {
    int n = threadIdx.x;
    const float* wc = w_comb + (size_t)n * 512;
    float s = b_comb[n];
#pragma unroll 4
    for (int j = 0; j < 256; ++j) s = fmaf(wc[j], b_out[j], s);
    bm[n] = s;
}

// ---------------- channel layernorm -> half xn ----------------
__global__ void cln_xn_kernel(const float* __restrict__ x,
                              const float* __restrict__ gamma, const float* __restrict__ beta,
                              __half* __restrict__ xn) {
    int b = blockIdx.x >> 5;
    int s = ((blockIdx.x & 31) * 256) + threadIdx.x;
    const float* p = x + (size_t)b * Cn * S_ + s;
    float sum = 0.f, sq = 0.f;
#pragma unroll 4
    for (int c = 0; c < Cn; ++c) {
        float v = p[(size_t)c * S_];
        sum += v; sq += v * v;
    }
    float m = sum * (1.f / Cn);
    float rs = rsqrtf(sq * (1.f / Cn) - m * m + EPSn);
    __half* q = xn + (size_t)b * Cn * S_ + s;
#pragma unroll 4
    for (int c = 0; c < Cn; ++c) {
        float v = (p[(size_t)c * S_] - m) * rs * gamma[c] + beta[c];
        q[(size_t)c * S_] = __float2half(v);
    }
}

// ---------------- half GEMM: Out[b,n,s] = sum_k W[n,k]*A[b,k,s]  (cp.async 3-stage) ----
// smem: W [128n][32k] rows of 64B, A [32k][128s] rows of 256B, XOR-swizzled, 3 stages = 48KB
template<bool RES, bool OH>
__global__ __launch_bounds__(256) void gemm_h_kernel(
    const __half* __restrict__ A, const __half* __restrict__ Wh,
    const float* __restrict__ bias, const float* __restrict__ resid,
    void* __restrict__ Outv, int K, int N)
{
    __shared__ __align__(16) __half Ws[3 * 128 * 32];
    __shared__ __align__(16) __half As[3 * 32 * 128];
    const int b  = blockIdx.z;
    const int s0 = blockIdx.x * 128;
    const int n0 = blockIdx.y * 128;
    const int t  = threadIdx.x;
    const int lane = t & 31, warp = t >> 5;
    const int wn = warp & 3, ws = warp >> 2;
    const int n0w = wn * 32, s0w = ws * 64;
    const int r = lane >> 2, c = lane & 3;

    float acc[2][8][4];
#pragma unroll
    for (int mt = 0; mt < 2; ++mt)
#pragma unroll
        for (int nt = 0; nt < 8; ++nt)
#pragma unroll
            for (int q = 0; q < 4; ++q) acc[mt][nt][q] = 0.f;

    const uint32_t wsB = smem_u32(Ws), asB = smem_u32(As);

    // cp.async destinations (swizzled)
    const int wn0 = t >> 2, wkc = t & 3;
    const int wswz = (wn0 >> 1) & 3;
    const uint32_t wdst0 = wsB + wn0 * 64 + ((wkc ^ wswz) * 16);
    const uint32_t wdst1 = wsB + (wn0 + 64) * 64 + ((wkc ^ wswz) * 16);
    const int ak = t >> 4, asc = t & 15;
    const uint32_t adst0 = asB + ak * 256 + ((asc ^ (ak & 7)) * 16);
    const uint32_t adst1 = asB + (ak + 16) * 256 + ((asc ^ (ak & 7)) * 16);
    const __half* wsrc0 = Wh + (size_t)(n0 + wn0) * K + wkc * 8;
    const __half* wsrc1 = Wh + (size_t)(n0 + wn0 + 64) * K + wkc * 8;
    const __half* asrc0 = A + ((size_t)b * K + ak) * S_ + s0 + asc * 8;
    const __half* asrc1 = A + ((size_t)b * K + ak + 16) * S_ + s0 + asc * 8;

    // ldmatrix source addresses
    uint32_t wbase[2]; int wswl[2];
    const int wch0 = lane >> 4;
#pragma unroll
    for (int mt = 0; mt < 2; ++mt) {
        int row = n0w + mt * 16 + (lane & 7) + ((lane >> 3) & 1) * 8;
        wbase[mt] = wsB + row * 64;
        wswl[mt] = (row >> 1) & 3;
    }
    uint32_t abase[4];
    {
        int k = (lane & 7) + ((lane >> 3) & 1) * 8;
#pragma unroll
        for (int ntp = 0; ntp < 4; ++ntp) {
            int chunk = (s0w >> 3) + ntp * 2 + (lane >> 4);
            abase[ntp] = asB + k * 256 + ((chunk ^ (k & 7)) * 16);
        }
    }

    auto issue = [&](int it) {
        int st = it % 3;
        uint32_t wo = st * 8192, ao = st * 8192;
        int k0 = it * 32;
        cp16(wdst0 + wo, wsrc0 + k0);
        cp16(wdst1 + wo, wsrc1 + k0);
        cp16(adst0 + ao, asrc0 + (size_t)k0 * S_);
        cp16(adst1 + ao, asrc1 + (size_t)k0 * S_);
    };

    auto compute = [&](int it) {
        int st = it % 3;
        uint32_t wo = st * 8192, ao = st * 8192;
#pragma unroll
        for (int ks = 0; ks < 2; ++ks) {
            uint32_t af[2][4];
#pragma unroll
            for (int mt = 0; mt < 2; ++mt) {
                uint32_t addr = wbase[mt] + wo + (uint32_t)((((wch0 + 2 * ks) ^ wswl[mt])) * 16);
                ldsm_x4(af[mt], addr);
            }
            uint32_t bf[8][2];
#pragma unroll
            for (int ntp = 0; ntp < 4; ++ntp) {
                uint32_t rr[4];
                ldsm_x4t(rr, abase[ntp] + ao + ks * 4096);
                bf[2 * ntp][0] = rr[0]; bf[2 * ntp][1] = rr[1];
                bf[2 * ntp + 1][0] = rr[2]; bf[2 * ntp + 1][1] = rr[3];
            }
#pragma unroll
            for (int mt = 0; mt < 2; ++mt)
#pragma unroll
                for (int nt = 0; nt < 8; ++nt)
                    mma_f16(acc[mt][nt], af[mt], bf[nt]);
        }
    };

    const int iters = K >> 5;
    issue(0); cp_commit();
    issue(1); cp_commit();
    for (int it = 0; it < iters; ++it) {
        if (it == iters - 1) cp_wait<0>(); else cp_wait<1>();
        __syncthreads();
        if (it + 2 < iters) { issue(it + 2); cp_commit(); }
        compute(it);
    }

    // epilogue
#pragma unroll
    for (int mt = 0; mt < 2; ++mt) {
#pragma unroll
        for (int half = 0; half < 2; ++half) {
            int n = n0 + n0w + mt * 16 + r + half * 8;
            float bv = (bias != nullptr) ? bias[n] : 0.f;
            const float* rrow = RES ? (resid + ((size_t)b * N + n) * S_) : nullptr;
#pragma unroll
            for (int nt = 0; nt < 8; ++nt) {
                int s = s0 + s0w + nt * 8 + 2 * c;
                float ox = acc[mt][nt][half * 2 + 0] + bv;
                float oy = acc[mt][nt][half * 2 + 1] + bv;
                if (RES) {
                    float2 rv = *reinterpret_cast<const float2*>(rrow + s);
                    ox += rv.x; oy += rv.y;
                }
                if (OH) {
                    __half* orow = (__half*)Outv + ((size_t)b * N + n) * S_;
                    *reinterpret_cast<__half2*>(orow + s) = __floats2half2_rn(ox, oy);
                } else {
                    float* orow = (float*)Outv + ((size_t)b * N + n) * S_;
                    float2 o; o.x = ox; o.y = oy;
                    *reinterpret_cast<float2*>(orow + s) = o;
                }
            }
        }
    }
}

// ---------------- L2 normalize q and k rows over W (fp32 qkv) ----------------
__global__ void l2norm_kernel(float* __restrict__ qkv) {
    int gw   = (blockIdx.x * blockDim.x + threadIdx.x) >> 5;
    int lane = threadIdx.x & 31;
    int x  = gw % H_;
    int ch = (gw / H_) % 512;
    int b  = gw / (H_ * 512);
    float* p = qkv + ((size_t)b * 768 + ch) * S_ + x * W_ + lane;
    float v = *p;
    float sq = v * v;
#pragma unroll
    for (int o = 16; o > 0; o >>= 1) sq += __shfl_xor_sync(0xffffffffu, sq, o);
    float nrm = fmaxf(sqrtf(sq), 1e-12f);
    *p = v / nrm;
}

// ---------------- q_probe partials ----------------
__global__ void qprobe_kernel(const float* __restrict__ qkv, float* __restrict__ qpart) {
    int bp = blockIdx.x;
    int bh = bp >> 3, part = bp & 7;
    int b = bh >> 3, head = bh & 7;
    int t = threadIdx.x, y = t & 31, sub = t >> 5;
    const float* base = qkv + ((size_t)b * 768 + head * 32) * S_;
    float acc = 0.f;
    for (int rr = sub * 128; rr < sub * 128 + 128; ++rr) {
        int dh = rr >> 5;
        int x  = part * 32 + (rr & 31);
        acc += base[(size_t)dh * S_ + x * 32 + y];
    }
    __shared__ float sh[256];
    sh[t] = acc;
    __syncthreads();
    if (t < 32) {
        float s = 0.f;
#pragma unroll
        for (int p = 0; p < 8; ++p) s += sh[p * 32 + t];
        qpart[bp * 32 + t] = s;
    }
}

// ---------------- ksumH[bh,dh,y] = sum_x kn ----------------
__global__ void ksumh_kernel(const float* __restrict__ qkv, float* __restrict__ ksumH) {
    int idx = blockIdx.x * blockDim.x + threadIdx.x;
    int y = idx & 31, dh = (idx >> 5) & 31, bh = idx >> 10;
    int b = bh >> 3, head = bh & 7;
    const float* p = qkv + ((size_t)b * 768 + 256 + head * 32 + dh) * S_ + y;
    float s = 0.f;
    for (int x = 0; x < H_; ++x) s += p[x * 32];
    ksumH[idx] = s;
}

// ---------------- top-k selection + gather ----------------
__global__ void select_kernel(const float* __restrict__ qkv,
                              const float* __restrict__ qpart,
                              const float* __restrict__ ksumH,
                              float* __restrict__ k2, float* __restrict__ v2) {
    int bh = blockIdx.x; int b = bh >> 3, head = bh & 7;
    int t = threadIdx.x;
    __shared__ float qp[32];
    __shared__ float shs[32];
    __shared__ int   ih[8];
    __shared__ float sws[256];
    __shared__ int   iw[8];

    if (t < 32) {
        float s = 0.f;
#pragma unroll
        for (int p = 0; p < 8; ++p) s += qpart[(bh * 8 + p) * 32 + t];
        qp[t] = s;
    }
    __syncthreads();
    if (t < 32) {
        float s = 0.f;
        const float* kr = ksumH + (bh * 32 + t) * 32;
#pragma unroll
        for (int y = 0; y < 32; ++y) s += qp[y] * kr[y];
        shs[t] = s;
    }
    __syncthreads();
    if (t == 0) {
        for (int j = 0; j < 8; ++j) {
            float best = -INFINITY; int bi = 0;
            for (int i = 0; i < 32; ++i)
                if (shs[i] > best) { best = shs[i]; bi = i; }
            ih[j] = bi; shs[bi] = -INFINITY;
        }
    }
    __syncthreads();
    {
        int x = t;
        float s = 0.f;
        const float* kbase = qkv + ((size_t)b * 768 + 256 + head * 32) * S_ + x * 32;
        for (int j = 0; j < 8; ++j) {
            const float* kp = kbase + (size_t)ih[j] * S_;
#pragma unroll
            for (int y = 0; y < 32; ++y) s += kp[y] * qp[y];
        }
        sws[x] = s;
    }
    __syncthreads();
    if (t == 0) {
        for (int j = 0; j < 8; ++j) {
            float best = -INFINITY; int bi = 0;
            for (int i = 0; i < 256; ++i)
                if (sws[i] > best) { best = sws[i]; bi = i; }
            iw[j] = bi; sws[bi] = -INFINITY;
        }
    }
    __syncthreads();
    for (int e = t; e < 64 * 32; e += 256) {
        int j = e >> 5, y = e & 31;
        int dh = ih[j >> 3], x = iw[j & 7];
        size_t koff = ((size_t)b * 768 + 256 + head * 32 + dh) * S_ + x * 32 + y;
        k2[(bh * 64 + j) * 32 + y] = qkv[koff];
        v2[(bh * 64 + j) * 32 + y] = qkv[koff + (size_t)256 * S_];
    }
}

// ---------------- attention -> half image, channels [0,256) of [b][512][S] ----------------
__global__ __launch_bounds__(256) void attn_kernel(const float* __restrict__ qkv,
                                                   const float* __restrict__ k2g,
                                                   const float* __restrict__ v2g,
                                                   __half* __restrict__ outimg) {
    int bh = blockIdx.y; int b = bh >> 3, head = bh & 7;
    int i0 = blockIdx.x * 32;
    int t = threadIdx.x, w = t >> 5, lane = t & 31;
    __shared__ float k2s[64 * 33];
    __shared__ float v2s[64 * 33];
    __shared__ float tile[32 * 33];
    for (int e = t; e < 64 * 32; e += 256) {
        int j = e >> 5, y = e & 31;
        k2s[j * 33 + y] = k2g[(bh * 64 + j) * 32 + y];
        v2s[j * 33 + y] = v2g[(bh * 64 + j) * 32 + y];
    }
    __syncthreads();
    const float* qbase = qkv + ((size_t)b * 768 + head * 32) * S_;
    for (int r = w; r < 32; r += 8) {
        int i  = i0 + r;
        int dh = i >> 8, x = i & 255;
        float qv = qbase[(size_t)dh * S_ + x * 32 + lane];
        float s0 = 0.f, s1 = 0.f;
#pragma unroll
        for (int y = 0; y < 32; ++y) {
            float qy = __shfl_sync(0xffffffffu, qv, y);
            s0 = fmaf(qy, k2s[lane * 33 + y], s0);
            s1 = fmaf(qy, k2s[(lane + 32) * 33 + y], s1);
        }
        float m = fmaxf(s0, s1);
#pragma unroll
        for (int o = 16; o > 0; o >>= 1) m = fmaxf(m, __shfl_xor_sync(0xffffffffu, m, o));
        float p0 = expf(s0 - m), p1 = expf(s1 - m);
        float sum = p0 + p1;
#pragma unroll
        for (int o = 16; o > 0; o >>= 1) sum += __shfl_xor_sync(0xffffffffu, sum, o);
        float inv = 1.f / sum;
        p0 *= inv; p1 *= inv;
        float o = 0.f;
#pragma unroll
        for (int j = 0; j < 32; ++j) {
            float pj = __shfl_sync(0xffffffffu, p0, j);
            o = fmaf(pj, v2s[j * 33 + lane], o);
        }
#pragma unroll
        for (int j = 0; j < 32; ++j) {
            float pj = __shfl_sync(0xffffffffu, p1, j);
            o = fmaf(pj, v2s[(j + 32) * 33 + lane], o);
        }
        tile[r * 33 + lane] = o;
    }
    __syncthreads();
    for (int e = t; e < 1024; e += 256) {
        int d = e >> 5, rr = e & 31;
        outimg[((size_t)b * 512 + head * 32 + d) * S_ + i0 + rr] = __float2half(tile[rr * 33 + d]);
    }
}

// ---------------- depthwise 3x3 on x -> half, channels [256,512) of [b][512][S] ----------
__global__ void dwconv_kernel(const float* __restrict__ in, const float* __restrict__ wgt,
                              const float* __restrict__ bias, __half* __restrict__ out) {
    int idx = blockIdx.x * blockDim.x + threadIdx.x;
    int s = idx & (S_ - 1);
    int c = (idx >> 13) & 255;
    int b = idx >> 21;
    int h = s >> 5, wv = s & 31;
    const float* p  = in + ((size_t)b * Cn + c) * S_;
    const float* wp = wgt + c * 9;
    float acc = bias[c];
#pragma unroll
    for (int dy = -1; dy <= 1; ++dy) {
        int h2 = h + dy;
        if (h2 < 0 || h2 >= H_) continue;
#pragma unroll
        for (int dx = -1; dx <= 1; ++dx) {
            int w2 = wv + dx;
            if (w2 < 0 || w2 >= W_) continue;
            acc = fmaf(wp[(dy + 1) * 3 + (dx + 1)], p[h2 * 32 + w2], acc);
        }
    }
    out[((size_t)b * 512 + 256 + c) * S_ + s] = __float2half(acc);
}

// ---------------- fused FF middle (half in/out) ----------------
__global__ __launch_bounds__(256) void ff_middle_kernel(
    const __half* __restrict__ ff1raw, const float* __restrict__ wgt,
    const float* __restrict__ bias, __half* __restrict__ h2out)
{
    __shared__ float img[S_];
    __shared__ float red1[256], red2[256];
    const int row = blockIdx.x;
    const int c   = row & (FFn - 1);
    const int t   = threadIdx.x;
    const __half* src = ff1raw + (size_t)row * S_;
    __half* dst = h2out + (size_t)row * S_;

    float sum = 0.f, sq = 0.f;
#pragma unroll
    for (int k = 0; k < 4; ++k) {
        uint4 raw = reinterpret_cast<const uint4*>(src)[t + k * 256];
        const __half2* h2p = reinterpret_cast<const __half2*>(&raw);
        int base = (t + k * 256) * 8;
#pragma unroll
        for (int q = 0; q < 4; ++q) {
            float2 f = __half22float2(h2p[q]);
            img[base + 2 * q] = f.x;
            img[base + 2 * q + 1] = f.y;
            sum += f.x + f.y;
            sq  += f.x * f.x + f.y * f.y;
        }
    }
    red1[t] = sum; red2[t] = sq; __syncthreads();
    for (int o = 128; o > 0; o >>= 1) {
        if (t < o) { red1[t] += red1[t + o]; red2[t] += red2[t + o]; }
        __syncthreads();
    }
    float m1 = red1[0] * (1.f / S_);
    float rs1 = rsqrtf(red2[0] * (1.f / S_) - m1 * m1 + EPSn);

#pragma unroll
    for (int k = 0; k < 8; ++k) {
        float4 v = reinterpret_cast<float4*>(img)[t + k * 256];
        v.x = gelu_f((v.x - m1) * rs1);
        v.y = gelu_f((v.y - m1) * rs1);
        v.z = gelu_f((v.z - m1) * rs1);
        v.w = gelu_f((v.w - m1) * rs1);
        reinterpret_cast<float4*>(img)[t + k * 256] = v;
    }
    __syncthreads();

    float wp[9];
#pragma unroll
    for (int j = 0; j < 9; ++j) wp[j] = wgt[c * 9 + j];
    float bv = bias[c];
    float o[32];
    float sum2 = 0.f, sq2 = 0.f;
#pragma unroll
    for (int k = 0; k < 32; ++k) {
        int idx = t + k * 256;
        int h = idx >> 5, wv = idx & 31;
        float acc = bv;
#pragma unroll
        for (int dy = -1; dy <= 1; ++dy) {
            int h2 = h + dy;
            if (h2 < 0 || h2 >= H_) continue;
#pragma unroll
            for (int dx = -1; dx <= 1; ++dx) {
                int w2 = wv + dx;
                if (w2 < 0 || w2 >= W_) continue;
                acc = fmaf(wp[(dy + 1) * 3 + (dx + 1)], img[h2 * 32 + w2], acc);
            }
        }
        o[k] = acc; sum2 += acc; sq2 += acc * acc;
    }
    __syncthreads();
    red1[t] = sum2; red2[t] = sq2; __syncthreads();
    for (int oo = 128; oo > 0; oo >>= 1) {
        if (t < oo) { red1[t] += red1[t + oo]; red2[t] += red2[t + oo]; }
        __syncthreads();
    }
    float m2 = red1[0] * (1.f / S_);
    float rs2 = rsqrtf(red2[0] * (1.f / S_) - m2 * m2 + EPSn);

#pragma unroll
    for (int k = 0; k < 32; ++k) {
        int idx = t + k * 256;
        dst[idx] = __float2half(img[idx] + gelu_f((o[k] - m2) * rs2));
    }
}

// ---------------- fused final instance norm ----------------
__global__ __launch_bounds__(256) void final_norm_kernel(
    const float* __restrict__ src, float* __restrict__ dst)
{
    __shared__ float red1[256], red2[256];
    const int row = blockIdx.x;
    const int t = threadIdx.x;
    const float4* s4 = reinterpret_cast<const float4*>(src + (size_t)row * S_);
    float4* d4 = reinterpret_cast<float4*>(dst + (size_t)row * S_);
    float4 loc[8];
    float sum = 0.f, sq = 0.f;
#pragma unroll
    for (int k = 0; k < 8; ++k) {
        float4 v = s4[t + k * 256];
        loc[k] = v;
        sum += v.x + v.y + v.z + v.w;
        sq  += v.x * v.x + v.y * v.y + v.z * v.z + v.w * v.w;
    }
    red1[t] = sum; red2[t] = sq; __syncthreads();
    for (int o = 128; o > 0; o >>= 1) {
        if (t < o) { red1[t] += red1[t + o]; red2[t] += red2[t + o]; }
        __syncthreads();
    }
    float m = red1[0] * (1.f / S_);
    float rs = rsqrtf(red2[0] * (1.f / S_) - m * m + EPSn);
#pragma unroll
    for (int k = 0; k < 8; ++k) {
        float4 v = loc[k];
        v.x = (v.x - m) * rs; v.y = (v.y - m) * rs;
        v.z = (v.z - m) * rs; v.w = (v.w - m) * rs;
        d4[t + k * 256] = v;
    }
}

// ---------------- host orchestration ----------------
extern "C" void kernel_launch(void* const* d_in, const int* in_sizes, int n_in,
                              void* d_out, int out_size) {
    const float* x      = (const float*)d_in[0];
    const float* cg     = (const float*)d_in[1];
    const float* cb     = (const float*)d_in[2];
    const float* w_qkv  = (const float*)d_in[3];
    const float* w_out  = (const float*)d_in[4];
    const float* b_out  = (const float*)d_in[5];
    const float* w_dw   = (const float*)d_in[6];
    const float* b_dw   = (const float*)d_in[7];
    const float* w_comb = (const float*)d_in[8];
    const float* b_comb = (const float*)d_in[9];
    const float* w_ff1  = (const float*)d_in[10];
    const float* b_ff1  = (const float*)d_in[11];
    const float* w_ffdw = (const float*)d_in[12];
    const float* b_ffdw = (const float*)d_in[13];
    const float* w_ff2  = (const float*)d_in[14];
    const float* b_ff2  = (const float*)d_in[15];
    float* out = (float*)d_out;

    float *qkv, *bufa, *bufb, *bufc, *ff1, *ffdw;
    float *qpart, *ksumH, *k2, *v2, *bm;
    __half *whqkv, *whcomb, *whff1, *whff2;
    void* p;
    cudaGetSymbolAddress(&p, g_qkv);    qkv    = (float*)p;
    cudaGetSymbolAddress(&p, g_bufa);   bufa   = (float*)p;
    cudaGetSymbolAddress(&p, g_bufb);   bufb   = (float*)p;
    cudaGetSymbolAddress(&p, g_bufc);   bufc   = (float*)p;
    cudaGetSymbolAddress(&p, g_ff1);    ff1    = (float*)p;
    cudaGetSymbolAddress(&p, g_ffdw);   ffdw   = (float*)p;
    cudaGetSymbolAddress(&p, g_qpart);  qpart  = (float*)p;
    cudaGetSymbolAddress(&p, g_ksumH);  ksumH  = (float*)p;
    cudaGetSymbolAddress(&p, g_k2);     k2     = (float*)p;
    cudaGetSymbolAddress(&p, g_v2);     v2     = (float*)p;
    cudaGetSymbolAddress(&p, g_bm);     bm     = (float*)p;
    cudaGetSymbolAddress(&p, g_whqkv);  whqkv  = (__half*)p;
    cudaGetSymbolAddress(&p, g_whcomb); whcomb = (__half*)p;
    cudaGetSymbolAddress(&p, g_whff1);  whff1  = (__half*)p;
    cudaGetSymbolAddress(&p, g_whff2);  whff2  = (__half*)p;

    __half* ov_h   = reinterpret_cast<__half*>(bufa);  // [b][512][S]
    __half* xn_h   = reinterpret_cast<__half*>(bufc);
    __half* comb_h = reinterpret_cast<__half*>(bufc);
    __half* ff1_h  = reinterpret_cast<__half*>(ff1);
    __half* h2_h   = reinterpret_cast<__half*>(ffdw);

    // 0) weight prep (half), merged comb weight/bias
    convert_w_kernel<<<768 * 256 / 256, 256>>>(w_qkv, whqkv, 768 * 256);
    convert_w_kernel<<<1024 * 256 / 256, 256>>>(w_ff1, whff1, 1024 * 256);
    convert_w_kernel<<<256 * 1024 / 256, 256>>>(w_ff2, whff2, 256 * 1024);
    wcombh_kernel<<<256, 256>>>(w_comb, w_out, whcomb);
    bmerge_kernel<<<1, 256>>>(w_comb, b_out, b_comb, bm);

    // 1) channel layernorm -> xn half
    cln_xn_kernel<<<Bn * 32, 256>>>(x, cg, cb, xn_h);

    // 2) qkv = W_qkv @ xn   (fp32 out)
    gemm_h_kernel<false, false><<<dim3(S_ / 128, 6, Bn), 256>>>(
        xn_h, whqkv, nullptr, nullptr, qkv, 256, 768);

    // 3) L2-normalize q and k rows
    l2norm_kernel<<<(Bn * 512 * H_) / 8, 256>>>(qkv);

    // 4) probe partials + key reductions
    qprobe_kernel<<<BHn * 8, 256>>>(qkv, qpart);
    ksumh_kernel<<<(BHn * 32 * 32) / 256, 256>>>(qkv, ksumH);

    // 5) top-k selection + gather
    select_kernel<<<BHn, 256>>>(qkv, qpart, ksumH, k2, v2);

    // 6) attention -> half image (channels 0..255 of bufa)
    attn_kernel<<<dim3(S_ / 32, BHn), 256>>>(qkv, k2, v2, ov_h);

    // 7) depthwise 3x3 on x -> half (channels 256..511 of bufa)
    dwconv_kernel<<<(Bn * Cn * S_) / 256, 256>>>(x, w_dw, b_dw, ov_h);

    // 8) comb = whcomb @ [o; dw] + bm + x  -> half (bufc)
    gemm_h_kernel<true, true><<<dim3(S_ / 128, 2, Bn), 256>>>(
        ov_h, whcomb, bm, x, comb_h, 512, 256);

    // 9) ff1 raw -> half
    gemm_h_kernel<false, true><<<dim3(S_ / 128, 8, Bn), 256>>>(
        comb_h, whff1, b_ff1, nullptr, ff1_h, 256, 1024);

    // 10) fused FF middle -> h2 half
    ff_middle_kernel<<<Bn * FFn, 256>>>(ff1_h, w_ffdw, b_ffdw, h2_h);

    // 11) ff2 -> fp32 (bufb); final instance norm -> out
    gemm_h_kernel<false, false><<<dim3(S_ / 128, 2, Bn), 256>>>(
        h2_h, whff2, b_ff2, nullptr, bufb, 1024, 256);
    final_norm_kernel<<<Bn * Cn, 256>>>(bufb, out);
}